// round 13
// baseline (speedup 1.0000x reference)
#include <cuda_runtime.h>
#include <cuda_fp16.h>
#include <cstdint>
#include <math.h>

// Problem constants
constexpr int BATCH  = 2;
constexpr int SEQ    = 2048;
constexpr int EMB    = 2048;
constexpr int NHEADS = 16;
constexpr int NKVH   = 4;
constexpr int HDIM   = 128;
constexpr int WIN    = 1024;
constexpr int GQA    = NHEADS / NKVH;

// fp32 scratch (pre-rope Q/K)
__device__ __align__(16) float g_Q [BATCH * SEQ * NHEADS * HDIM];
__device__ __align__(16) float g_K [BATCH * SEQ * NKVH   * HDIM];
// fp16 (half2-in-u32) scratch
__device__ __align__(16) uint32_t g_xh [BATCH * SEQ * (EMB / 2)];
__device__ __align__(16) uint32_t g_Wqh[EMB * (EMB / 2)];
__device__ __align__(16) uint32_t g_Wkh[NKVH * HDIM * (EMB / 2)];
__device__ __align__(16) uint32_t g_Wvh[NKVH * HDIM * (EMB / 2)];
__device__ __align__(16) uint32_t g_Woh[EMB * (EMB / 2)];
__device__ __align__(16) uint32_t g_Qh [BATCH * SEQ * NHEADS * (HDIM / 2)];  // pre-scaled
__device__ __align__(16) uint32_t g_Kh [BATCH * SEQ * NKVH   * (HDIM / 2)];
__device__ __align__(16) __half   g_Vth[BATCH * NKVH * HDIM * SEQ];          // [b][kvh][d][s]
__device__ __align__(16) uint32_t g_AOh[BATCH * SEQ * (EMB / 2)];

__device__ __forceinline__ uint32_t pack2(float lo, float hi) {
    uint32_t r;
    asm("cvt.rn.f16x2.f32 %0, %1, %2;" : "=r"(r) : "f"(hi), "f"(lo));
    return r;
}
__device__ __forceinline__ float ex2(float x) {
    float r;
    asm("ex2.approx.f32 %0, %1;" : "=f"(r) : "f"(x));
    return r;
}
__device__ __forceinline__ void mma_f16(
    float& d0, float& d1, float& d2, float& d3,
    uint32_t a0, uint32_t a1, uint32_t a2, uint32_t a3,
    uint32_t b0, uint32_t b1)
{
    asm volatile(
        "mma.sync.aligned.m16n8k16.row.col.f32.f16.f16.f32 "
        "{%0,%1,%2,%3}, {%4,%5,%6,%7}, {%8,%9}, {%0,%1,%2,%3};"
        : "+f"(d0), "+f"(d1), "+f"(d2), "+f"(d3)
        : "r"(a0), "r"(a1), "r"(a2), "r"(a3), "r"(b0), "r"(b1));
}
__device__ __forceinline__ void cp16(uint32_t saddr, const void* gptr) {
    asm volatile("cp.async.cg.shared.global [%0], [%1], 16;"
                 :: "r"(saddr), "l"(gptr));
}

// ---------------------------------------------------------------------------
// fp32 -> fp16x2 bulk convert
// ---------------------------------------------------------------------------
__global__ void cvt_h_kernel(const float4* __restrict__ src,
                             uint2* __restrict__ dst, int n4)
{
    int i = blockIdx.x * blockDim.x + threadIdx.x;
    if (i >= n4) return;
    float4 v = src[i];
    dst[i] = make_uint2(pack2(v.x, v.y), pack2(v.z, v.w));
}

// ===========================================================================
// FP16 GEMM (NT) — unchanged (at legacy-HMMA ceiling).
// ===========================================================================
constexpr int SAPADH = 36;
constexpr int TILE_H = 128 * SAPADH;
constexpr int NSTG = 3;
constexpr int SMEM_GEMM = NSTG * 2 * TILE_H * 4;

template<int VMODE>
__device__ __forceinline__ void gemm_body_f16(
    const uint32_t* __restrict__ A, const uint32_t* __restrict__ B,
    float* __restrict__ C, __half* __restrict__ Vt,
    int M, int N, int K, int bx, int by, uint32_t* smem)
{
    const int K2 = K / 2;
    const int tid  = threadIdx.x;
    const int lane = tid & 31;
    const int wid  = tid >> 5;
    const int m0 = by * 128;
    const int n0 = bx * 128;

    const int wm  = (wid >> 2) * 64;
    const int wn  = (wid & 3) * 32;
    const int gID = lane >> 2;
    const int tig = lane & 3;

    const int lr0 = tid >> 3;
    const int lc4 = tid & 7;

    const uint32_t* Abase = A + (size_t)(m0 + lr0) * K2 + lc4 * 4;
    const uint32_t* Bbase = B + (size_t)(n0 + lr0) * K2 + lc4 * 4;
    const uint32_t sbase = (uint32_t)__cvta_generic_to_shared(smem);

    float acc[4][4][4];
#pragma unroll
    for (int mi = 0; mi < 4; ++mi)
#pragma unroll
        for (int ni = 0; ni < 4; ++ni)
#pragma unroll
            for (int q = 0; q < 4; ++q) acc[mi][ni][q] = 0.f;

    const int nch = K / 64;

    auto issue = [&](int c) {
        const uint32_t st = sbase + (uint32_t)((c % NSTG) * 2 * TILE_H) * 4;
        const int kb = c * 32;
#pragma unroll
        for (int j = 0; j < 4; ++j) {
            int r = lr0 + 32 * j;
            cp16(st + (uint32_t)(r * SAPADH + lc4 * 4) * 4,
                 Abase + (size_t)(32 * j) * K2 + kb);
            cp16(st + (uint32_t)(TILE_H + r * SAPADH + lc4 * 4) * 4,
                 Bbase + (size_t)(32 * j) * K2 + kb);
        }
        asm volatile("cp.async.commit_group;");
    };

    issue(0);
    issue(1);

    for (int c = 0; c < nch; ++c) {
        if (c + 1 < nch) asm volatile("cp.async.wait_group 1;");
        else             asm volatile("cp.async.wait_group 0;");
        __syncthreads();

        const uint32_t* sA = smem + (c % NSTG) * 2 * TILE_H;
        const uint32_t* sB = sA + TILE_H;
#pragma unroll
        for (int ks = 0; ks < 4; ++ks) {
            const int kq = ks * 8;
            uint32_t af[4][4], bf[4][2];
#pragma unroll
            for (int mi = 0; mi < 4; ++mi) {
                int row = wm + mi * 16 + gID;
                af[mi][0] = sA[row * SAPADH + kq + tig];
                af[mi][1] = sA[(row + 8) * SAPADH + kq + tig];
                af[mi][2] = sA[row * SAPADH + kq + tig + 4];
                af[mi][3] = sA[(row + 8) * SAPADH + kq + tig + 4];
            }
#pragma unroll
            for (int ni = 0; ni < 4; ++ni) {
                int col = wn + ni * 8 + gID;
                bf[ni][0] = sB[col * SAPADH + kq + tig];
                bf[ni][1] = sB[col * SAPADH + kq + tig + 4];
            }
#pragma unroll
            for (int mi = 0; mi < 4; ++mi)
#pragma unroll
                for (int ni = 0; ni < 4; ++ni)
                    mma_f16(acc[mi][ni][0], acc[mi][ni][1], acc[mi][ni][2], acc[mi][ni][3],
                            af[mi][0], af[mi][1], af[mi][2], af[mi][3],
                            bf[ni][0], bf[ni][1]);
        }

        if (c + 2 < nch) issue(c + 2);
    }

    if (VMODE == 0) {
#pragma unroll
        for (int mi = 0; mi < 4; ++mi) {
            int row = m0 + wm + mi * 16 + gID;
#pragma unroll
            for (int ni = 0; ni < 4; ++ni) {
                int col = n0 + wn + ni * 8 + tig * 2;
                *reinterpret_cast<float2*>(C + (size_t)row * N + col) =
                    make_float2(acc[mi][ni][0], acc[mi][ni][1]);
                *reinterpret_cast<float2*>(C + (size_t)(row + 8) * N + col) =
                    make_float2(acc[mi][ni][2], acc[mi][ni][3]);
            }
        }
    } else {
#pragma unroll
        for (int mi = 0; mi < 4; ++mi) {
            int row = m0 + wm + mi * 16 + gID;
            int b0i = row >> 11, s0i = row & 2047;
            int b1i = (row + 8) >> 11, s1i = (row + 8) & 2047;
#pragma unroll
            for (int ni = 0; ni < 4; ++ni) {
                int col = n0 + wn + ni * 8 + tig * 2;
#pragma unroll
                for (int cc = 0; cc < 2; ++cc) {
                    int n = col + cc;
                    int kv = n >> 7, d = n & 127;
                    size_t base = ((size_t)(b0i * NKVH + kv) * HDIM + d) * SEQ;
                    Vt[base + s0i] = __float2half_rn(acc[mi][ni][cc]);
                    size_t base1 = ((size_t)(b1i * NKVH + kv) * HDIM + d) * SEQ;
                    Vt[base1 + s1i] = __float2half_rn(acc[mi][ni][cc + 2]);
                }
            }
        }
    }
}

__global__ __launch_bounds__(256, 2) void gemm_f16(
    const uint32_t* __restrict__ A, const uint32_t* __restrict__ B,
    float* __restrict__ C, int M, int N, int K)
{
    extern __shared__ uint32_t smem[];
    gemm_body_f16<0>(A, B, C, nullptr, M, N, K, blockIdx.x, blockIdx.y, smem);
}

__global__ __launch_bounds__(256, 2) void gemm_kv_f16(
    const uint32_t* __restrict__ A,
    const uint32_t* __restrict__ Wk, const uint32_t* __restrict__ Wv,
    float* __restrict__ Kout, __half* __restrict__ Vt,
    int M, int N, int K)
{
    extern __shared__ uint32_t smem[];
    if (blockIdx.z == 0)
        gemm_body_f16<0>(A, Wk, Kout, nullptr, M, N, K, blockIdx.x, blockIdx.y, smem);
    else
        gemm_body_f16<1>(A, Wv, nullptr, Vt, M, N, K, blockIdx.x, blockIdx.y, smem);
}

// ---------------------------------------------------------------------------
// RoPE: fp32 in, pre-scaled fp16 out.
// ---------------------------------------------------------------------------
__global__ void rope_kernel(const float* __restrict__ cosb,
                            const float* __restrict__ sinb)
{
    const int total = BATCH * SEQ * (NHEADS + NKVH) * 32;
    int idx = blockIdx.x * blockDim.x + threadIdx.x;
    if (idx >= total) return;
    int e    = idx & 31;
    int rest = idx >> 5;
    int slot = rest % (NHEADS + NKVH);
    int bs   = rest / (NHEADS + NKVH);
    int s    = bs % SEQ;

    const float2* cp = reinterpret_cast<const float2*>(cosb + s * HDIM);
    const float2* sp = reinterpret_cast<const float2*>(sinb + s * HDIM);
    float2 c0 = cp[e], c1 = cp[e + 32];
    float2 s0 = sp[e], s1 = sp[e + 32];

    const float2* p;
    uint32_t* o;
    float mult;
    if (slot < NHEADS) {
        p = reinterpret_cast<const float2*>(g_Q + (size_t)(bs * NHEADS + slot) * HDIM);
        o = g_Qh + (size_t)(bs * NHEADS + slot) * 64;
        mult = 0.08838834764831845f * 1.4426950408889634f;
    } else {
        p = reinterpret_cast<const float2*>(g_K + (size_t)(bs * NKVH + (slot - NHEADS)) * HDIM);
        o = g_Kh + (size_t)(bs * NKVH + (slot - NHEADS)) * 64;
        mult = 1.0f;
    }

    float2 x0 = p[e];
    float2 x1 = p[e + 32];
    float o0x = x0.x * c0.x - x1.x * s0.x;
    float o0y = x0.y * c0.y - x1.y * s0.y;
    float o1x = x1.x * c1.x + x0.x * s1.x;
    float o1y = x1.y * c1.y + x0.y * s1.y;
    o[e]      = pack2(o0x * mult, o0y * mult);
    o[e + 32] = pack2(o1x * mult, o1y * mult);
}

// ===========================================================================
// FP16 MMA flash attention: 2 heads x 32 queries per CTA, 64-KEY KV TILES.
// 128 threads, 4 warps. KV shared across the 2 heads; double-buffered cp.async.
// ===========================================================================
constexpr int KTILE = 64;
constexpr int KSTRH = 68;    // K tile row stride (u32)
constexpr int VSTRH = 36;    // Vt tile row stride (32 data + 4 pad)
constexpr int QSTRH = 68;
constexpr int PSTRH = 36;

constexpr int AKS0 = 0;                         // K buf: 64*68 = 4352
constexpr int AKS1 = AKS0 + KTILE * KSTRH;      // 4352
constexpr int AVS0 = AKS1 + KTILE * KSTRH;      // 8704 ; V buf: 128*36 = 4608
constexpr int AVS1 = AVS0 + 128 * VSTRH;        // 13312
constexpr int AQS  = AVS1 + 128 * VSTRH;        // 17920; Q: 64*68 = 4352
constexpr int APS  = AQS + 64 * QSTRH;          // 22272; P: 4*16*36 = 2304
constexpr int SMEM_ATTN = (APS + 4 * 16 * PSTRH) * 4;   // 98304 B

__global__ __launch_bounds__(128) void attn_f16_kernel()
{
    extern __shared__ uint32_t sm[];

    const int tid  = threadIdx.x;
    const int lane = tid & 31;
    const int wid  = tid >> 5;          // 0..3
    const int hl   = wid >> 1;
    const int sub  = wid & 1;
    const int g    = lane >> 2;
    const int t    = lane & 3;

    const int q0  = blockIdx.x * 32;
    const int hp  = blockIdx.y;
    const int kvh = hp >> 1;
    const int b   = blockIdx.z;
    const int h   = hp * 2 + hl;
    const int bS  = b * SEQ;
    const int qw  = q0 + sub * 16;

    const uint32_t sbase = (uint32_t)__cvta_generic_to_shared(sm);

    // ---- stage Q tiles for the 2 heads ----
#pragma unroll
    for (int i = tid; i < 1024; i += 128) {
        int ih = i >> 9;
        int r  = (i >> 4) & 31;
        int ch = i & 15;
        const uint32_t* src = g_Qh +
            ((size_t)(bS + q0 + r) * NHEADS + hp * 2 + ih) * 64 + ch * 4;
        cp16(sbase + (uint32_t)(AQS + (ih * 32 + r) * QSTRH + ch * 4) * 4, src);
    }
    asm volatile("cp.async.commit_group;");

    // ---- first K/V tile ----
    int jstart = q0 - (WIN - 1);
    if (jstart < 0) jstart = 0;
    jstart &= ~(KTILE - 1);
    const int nt = (q0 + 32 - jstart + KTILE - 1) >> 6;

    auto stage_kv = [&](int j0, int buf) {
        const int ko = buf ? AKS1 : AKS0;
        const int vo = buf ? AVS1 : AVS0;
#pragma unroll
        for (int i = tid; i < 1024; i += 128) {   // K: 64 rows x 16 chunks
            int r = i >> 4, ch = i & 15;
            const uint32_t* src = g_Kh + ((size_t)(bS + j0 + r) * NKVH + kvh) * 64 + ch * 4;
            cp16(sbase + (uint32_t)(ko + r * KSTRH + ch * 4) * 4, src);
        }
        const uint32_t* Vt = reinterpret_cast<const uint32_t*>(g_Vth) +
            ((size_t)(b * NKVH + kvh) * HDIM) * (SEQ / 2);
#pragma unroll
        for (int i = tid; i < 1024; i += 128) {   // V: 128 d-rows x 8 chunks
            int d = i >> 3, ch = i & 7;
            const uint32_t* src = Vt + (size_t)d * (SEQ / 2) + (j0 >> 1) + ch * 4;
            cp16(sbase + (uint32_t)(vo + d * VSTRH + ch * 4) * 4, src);
        }
        asm volatile("cp.async.commit_group;");
    };

    stage_kv(jstart, 0);

    asm volatile("cp.async.wait_group 1;");
    __syncthreads();
    uint32_t qf[8][4];
#pragma unroll
    for (int kk = 0; kk < 8; ++kk) {
        int r0 = AQS + (hl * 32 + sub * 16 + g) * QSTRH + kk * 8 + t;
        qf[kk][0] = sm[r0];
        qf[kk][1] = sm[r0 + 8 * QSTRH];
        qf[kk][2] = sm[r0 + 4];
        qf[kk][3] = sm[r0 + 8 * QSTRH + 4];
    }

    uint32_t* Pw = &sm[APS + wid * 16 * PSTRH];

    float m0r = -1e30f, m1r = -1e30f, l0 = 0.f, l1 = 0.f;
    float oacc[16][4];
#pragma unroll
    for (int ni = 0; ni < 16; ++ni)
#pragma unroll
        for (int qd = 0; qd < 4; ++qd) oacc[ni][qd] = 0.f;

    for (int it = 0; it < nt; ++it) {
        const int j0 = jstart + it * KTILE;
        if (it + 1 < nt) {
            stage_kv(j0 + KTILE, (it + 1) & 1);
            asm volatile("cp.async.wait_group 1;");
        } else {
            asm volatile("cp.async.wait_group 0;");
        }
        __syncthreads();

        const bool active = (j0 <= qw + 15) && (qw - (j0 + KTILE - 1) < WIN);
        if (active) {
            const uint32_t* Ks = &sm[(it & 1) ? AKS1 : AKS0];
            const uint32_t* Vs = &sm[(it & 1) ? AVS1 : AVS0];

            // ---- QK^T over 64 keys ----
            float sc[8][4];
#pragma unroll
            for (int ni = 0; ni < 8; ++ni)
#pragma unroll
                for (int qd = 0; qd < 4; ++qd) sc[ni][qd] = 0.f;

#pragma unroll
            for (int kk = 0; kk < 8; ++kk) {
#pragma unroll
                for (int ni = 0; ni < 8; ++ni) {
                    uint32_t b0 = Ks[(ni * 8 + g) * KSTRH + kk * 8 + t];
                    uint32_t b1 = Ks[(ni * 8 + g) * KSTRH + kk * 8 + t + 4];
                    mma_f16(sc[ni][0], sc[ni][1], sc[ni][2], sc[ni][3],
                            qf[kk][0], qf[kk][1], qf[kk][2], qf[kk][3], b0, b1);
                }
            }

            // ---- mask + row max ----
            const int r0 = qw + g;
            float tmax0 = -1e30f, tmax1 = -1e30f;
#pragma unroll
            for (int ni = 0; ni < 8; ++ni) {
                int col0 = j0 + ni * 8 + 2 * t;
#pragma unroll
                for (int cc = 0; cc < 2; ++cc) {
                    int col = col0 + cc;
                    int d0 = r0 - col;
                    int d1 = r0 + 8 - col;
                    if (!(d0 >= 0 && d0 < WIN)) sc[ni][cc]     = -1e30f;
                    if (!(d1 >= 0 && d1 < WIN)) sc[ni][cc + 2] = -1e30f;
                    tmax0 = fmaxf(tmax0, sc[ni][cc]);
                    tmax1 = fmaxf(tmax1, sc[ni][cc + 2]);
                }
            }
            tmax0 = fmaxf(tmax0, __shfl_xor_sync(0xffffffffu, tmax0, 1));
            tmax0 = fmaxf(tmax0, __shfl_xor_sync(0xffffffffu, tmax0, 2));
            tmax1 = fmaxf(tmax1, __shfl_xor_sync(0xffffffffu, tmax1, 1));
            tmax1 = fmaxf(tmax1, __shfl_xor_sync(0xffffffffu, tmax1, 2));

            float mn0 = fmaxf(m0r, tmax0);
            float mn1 = fmaxf(m1r, tmax1);
            float cor0 = ex2(m0r - mn0);
            float cor1 = ex2(m1r - mn1);
            m0r = mn0; m1r = mn1;

            float ps0 = 0.f, ps1 = 0.f;
#pragma unroll
            for (int ni = 0; ni < 8; ++ni) {
                float p00 = (sc[ni][0] > -1e29f) ? ex2(sc[ni][0] - mn0) : 0.f;
                float p01 = (sc[ni][1] > -1e29f) ? ex2(sc[ni][1] - mn0) : 0.f;
                float p10 = (sc[ni][2] > -1e29f) ? ex2(sc[ni][2] - mn1) : 0.f;
                float p11 = (sc[ni][3] > -1e29f) ? ex2(sc[ni][3] - mn1) : 0.f;
                ps0 += p00 + p01;
                ps1 += p10 + p11;
                Pw[g * PSTRH + ni * 4 + t]       = pack2(p00, p01);
                Pw[(g + 8) * PSTRH + ni * 4 + t] = pack2(p10, p11);
            }
            ps0 += __shfl_xor_sync(0xffffffffu, ps0, 1);
            ps0 += __shfl_xor_sync(0xffffffffu, ps0, 2);
            ps1 += __shfl_xor_sync(0xffffffffu, ps1, 1);
            ps1 += __shfl_xor_sync(0xffffffffu, ps1, 2);
            l0 = l0 * cor0 + ps0;
            l1 = l1 * cor1 + ps1;

#pragma unroll
            for (int ni = 0; ni < 16; ++ni) {
                oacc[ni][0] *= cor0; oacc[ni][1] *= cor0;
                oacc[ni][2] *= cor1; oacc[ni][3] *= cor1;
            }

            __syncwarp();

            // ---- PV: out += P[16x64] * V[64x128] ----
#pragma unroll
            for (int kc = 0; kc < 4; ++kc) {      // four k16 steps
                uint32_t a0 = Pw[g * PSTRH + kc * 8 + t];
                uint32_t a1 = Pw[(g + 8) * PSTRH + kc * 8 + t];
                uint32_t a2 = Pw[g * PSTRH + kc * 8 + t + 4];
                uint32_t a3 = Pw[(g + 8) * PSTRH + kc * 8 + t + 4];
#pragma unroll
                for (int ni = 0; ni < 16; ++ni) {
                    uint32_t b0 = Vs[(ni * 8 + g) * VSTRH + kc * 8 + t];
                    uint32_t b1 = Vs[(ni * 8 + g) * VSTRH + kc * 8 + t + 4];
                    mma_f16(oacc[ni][0], oacc[ni][1], oacc[ni][2], oacc[ni][3],
                            a0, a1, a2, a3, b0, b1);
                }
            }
            __syncwarp();
        }
        __syncthreads();
    }

    // ---- normalize + store half2 for O-projection ----
    float inv0 = 1.f / l0;
    float inv1 = 1.f / l1;
    uint32_t* Ot  = g_AOh + ((size_t)(bS + qw + g) * NHEADS + h) * 64;
    uint32_t* Ot8 = Ot + (size_t)8 * NHEADS * 64;
#pragma unroll
    for (int ni = 0; ni < 16; ++ni) {
        Ot[ni * 4 + t]  = pack2(oacc[ni][0] * inv0, oacc[ni][1] * inv0);
        Ot8[ni * 4 + t] = pack2(oacc[ni][2] * inv1, oacc[ni][3] * inv1);
    }
}

// ---------------------------------------------------------------------------
// Launch
// ---------------------------------------------------------------------------
extern "C" void kernel_launch(void* const* d_in, const int* in_sizes, int n_in,
                              void* d_out, int out_size)
{
    const float* x    = (const float*)d_in[0];
    const float* cosb = (const float*)d_in[1];
    const float* sinb = (const float*)d_in[2];
    const float* Wq   = (const float*)d_in[3];
    const float* Wk   = (const float*)d_in[4];
    const float* Wv   = (const float*)d_in[5];
    const float* Wo   = (const float*)d_in[6];
    float* out = (float*)d_out;

    float *Q, *K;
    uint32_t *xh, *Wqh, *Wkh, *Wvh, *Woh, *AOh;
    __half* Vth;
    cudaGetSymbolAddress((void**)&Q,   g_Q);
    cudaGetSymbolAddress((void**)&K,   g_K);
    cudaGetSymbolAddress((void**)&xh,  g_xh);
    cudaGetSymbolAddress((void**)&Wqh, g_Wqh);
    cudaGetSymbolAddress((void**)&Wkh, g_Wkh);
    cudaGetSymbolAddress((void**)&Wvh, g_Wvh);
    cudaGetSymbolAddress((void**)&Woh, g_Woh);
    cudaGetSymbolAddress((void**)&AOh, g_AOh);
    cudaGetSymbolAddress((void**)&Vth, g_Vth);

    static bool attr_done = false;
    if (!attr_done) {
        cudaFuncSetAttribute(gemm_f16,    cudaFuncAttributeMaxDynamicSharedMemorySize, SMEM_GEMM);
        cudaFuncSetAttribute(gemm_kv_f16, cudaFuncAttributeMaxDynamicSharedMemorySize, SMEM_GEMM);
        cudaFuncSetAttribute(attn_f16_kernel, cudaFuncAttributeMaxDynamicSharedMemorySize, SMEM_ATTN);
        attr_done = true;
    }

    const int M = BATCH * SEQ;

    auto cvt = [](const float* s, uint32_t* d, int n) {
        int n4 = n / 4;
        cvt_h_kernel<<<(n4 + 255) / 256, 256>>>(
            reinterpret_cast<const float4*>(s), reinterpret_cast<uint2*>(d), n4);
    };
    cvt(x,  xh,  BATCH * SEQ * EMB);
    cvt(Wq, Wqh, EMB * EMB);
    cvt(Wk, Wkh, NKVH * HDIM * EMB);
    cvt(Wv, Wvh, NKVH * HDIM * EMB);
    cvt(Wo, Woh, EMB * EMB);

    gemm_f16<<<dim3(EMB / 128, M / 128), 256, SMEM_GEMM>>>(xh, Wqh, Q, M, NHEADS * HDIM, EMB);
    gemm_kv_f16<<<dim3((NKVH * HDIM) / 128, M / 128, 2), 256, SMEM_GEMM>>>(
        xh, Wkh, Wvh, K, Vth, M, NKVH * HDIM, EMB);

    {
        int total = BATCH * SEQ * (NHEADS + NKVH) * 32;
        rope_kernel<<<(total + 255) / 256, 256>>>(cosb, sinb);
    }

    attn_f16_kernel<<<dim3(SEQ / 32, NHEADS / 2, BATCH), 128, SMEM_ATTN>>>();

    gemm_f16<<<dim3(EMB / 128, M / 128), 256, SMEM_GEMM>>>(AOh, Woh, out, M, EMB, EMB);
}

// round 14
// speedup vs baseline: 1.1481x; 1.1481x over previous
#include <cuda_runtime.h>
#include <cuda_fp16.h>
#include <cstdint>
#include <math.h>

// Problem constants
constexpr int BATCH  = 2;
constexpr int SEQ    = 2048;
constexpr int EMB    = 2048;
constexpr int NHEADS = 16;
constexpr int NKVH   = 4;
constexpr int HDIM   = 128;
constexpr int WIN    = 1024;
constexpr int GQA    = NHEADS / NKVH;

// fp32 scratch (pre-rope Q/K)
__device__ __align__(16) float g_Q [BATCH * SEQ * NHEADS * HDIM];
__device__ __align__(16) float g_K [BATCH * SEQ * NKVH   * HDIM];
// fp16 (half2-in-u32) scratch
__device__ __align__(16) uint32_t g_xh [BATCH * SEQ * (EMB / 2)];
__device__ __align__(16) uint32_t g_Wqh[EMB * (EMB / 2)];
__device__ __align__(16) uint32_t g_Wkh[NKVH * HDIM * (EMB / 2)];
__device__ __align__(16) uint32_t g_Wvh[NKVH * HDIM * (EMB / 2)];
__device__ __align__(16) uint32_t g_Woh[EMB * (EMB / 2)];
__device__ __align__(16) uint32_t g_Qh [BATCH * SEQ * NHEADS * (HDIM / 2)];  // pre-scaled
__device__ __align__(16) uint32_t g_Kh [BATCH * SEQ * NKVH   * (HDIM / 2)];
__device__ __align__(16) __half   g_Vth[BATCH * NKVH * HDIM * SEQ];          // [b][kvh][d][s]
__device__ __align__(16) uint32_t g_AOh[BATCH * SEQ * (EMB / 2)];

__device__ __forceinline__ uint32_t pack2(float lo, float hi) {
    uint32_t r;
    asm("cvt.rn.f16x2.f32 %0, %1, %2;" : "=r"(r) : "f"(hi), "f"(lo));
    return r;
}
__device__ __forceinline__ float ex2(float x) {
    float r;
    asm("ex2.approx.f32 %0, %1;" : "=f"(r) : "f"(x));
    return r;
}
__device__ __forceinline__ void mma_f16(
    float& d0, float& d1, float& d2, float& d3,
    uint32_t a0, uint32_t a1, uint32_t a2, uint32_t a3,
    uint32_t b0, uint32_t b1)
{
    asm volatile(
        "mma.sync.aligned.m16n8k16.row.col.f32.f16.f16.f32 "
        "{%0,%1,%2,%3}, {%4,%5,%6,%7}, {%8,%9}, {%0,%1,%2,%3};"
        : "+f"(d0), "+f"(d1), "+f"(d2), "+f"(d3)
        : "r"(a0), "r"(a1), "r"(a2), "r"(a3), "r"(b0), "r"(b1));
}
__device__ __forceinline__ void cp16(uint32_t saddr, const void* gptr) {
    asm volatile("cp.async.cg.shared.global [%0], [%1], 16;"
                 :: "r"(saddr), "l"(gptr));
}

// ---------------------------------------------------------------------------
// fp32 -> fp16x2 bulk convert (single tensor, and paired via grid.z)
// ---------------------------------------------------------------------------
__global__ void cvt_h_kernel(const float4* __restrict__ src,
                             uint2* __restrict__ dst, int n4)
{
    int i = blockIdx.x * blockDim.x + threadIdx.x;
    if (i >= n4) return;
    float4 v = src[i];
    dst[i] = make_uint2(pack2(v.x, v.y), pack2(v.z, v.w));
}

__global__ void cvt_h2_kernel(const float4* __restrict__ s0, uint2* __restrict__ d0,
                              const float4* __restrict__ s1, uint2* __restrict__ d1,
                              int n4)
{
    int i = blockIdx.x * blockDim.x + threadIdx.x;
    if (i >= n4) return;
    const float4* s = blockIdx.z ? s1 : s0;
    uint2* d        = blockIdx.z ? d1 : d0;
    float4 v = s[i];
    d[i] = make_uint2(pack2(v.x, v.y), pack2(v.z, v.w));
}

// ===========================================================================
// FP16 GEMM (NT) — unchanged (at legacy-HMMA ceiling).
// ===========================================================================
constexpr int SAPADH = 36;
constexpr int TILE_H = 128 * SAPADH;
constexpr int NSTG = 3;
constexpr int SMEM_GEMM = NSTG * 2 * TILE_H * 4;

template<int VMODE>
__device__ __forceinline__ void gemm_body_f16(
    const uint32_t* __restrict__ A, const uint32_t* __restrict__ B,
    float* __restrict__ C, __half* __restrict__ Vt,
    int M, int N, int K, int bx, int by, uint32_t* smem)
{
    const int K2 = K / 2;
    const int tid  = threadIdx.x;
    const int lane = tid & 31;
    const int wid  = tid >> 5;
    const int m0 = by * 128;
    const int n0 = bx * 128;

    const int wm  = (wid >> 2) * 64;
    const int wn  = (wid & 3) * 32;
    const int gID = lane >> 2;
    const int tig = lane & 3;

    const int lr0 = tid >> 3;
    const int lc4 = tid & 7;

    const uint32_t* Abase = A + (size_t)(m0 + lr0) * K2 + lc4 * 4;
    const uint32_t* Bbase = B + (size_t)(n0 + lr0) * K2 + lc4 * 4;
    const uint32_t sbase = (uint32_t)__cvta_generic_to_shared(smem);

    float acc[4][4][4];
#pragma unroll
    for (int mi = 0; mi < 4; ++mi)
#pragma unroll
        for (int ni = 0; ni < 4; ++ni)
#pragma unroll
            for (int q = 0; q < 4; ++q) acc[mi][ni][q] = 0.f;

    const int nch = K / 64;

    auto issue = [&](int c) {
        const uint32_t st = sbase + (uint32_t)((c % NSTG) * 2 * TILE_H) * 4;
        const int kb = c * 32;
#pragma unroll
        for (int j = 0; j < 4; ++j) {
            int r = lr0 + 32 * j;
            cp16(st + (uint32_t)(r * SAPADH + lc4 * 4) * 4,
                 Abase + (size_t)(32 * j) * K2 + kb);
            cp16(st + (uint32_t)(TILE_H + r * SAPADH + lc4 * 4) * 4,
                 Bbase + (size_t)(32 * j) * K2 + kb);
        }
        asm volatile("cp.async.commit_group;");
    };

    issue(0);
    issue(1);

    for (int c = 0; c < nch; ++c) {
        if (c + 1 < nch) asm volatile("cp.async.wait_group 1;");
        else             asm volatile("cp.async.wait_group 0;");
        __syncthreads();

        const uint32_t* sA = smem + (c % NSTG) * 2 * TILE_H;
        const uint32_t* sB = sA + TILE_H;
#pragma unroll
        for (int ks = 0; ks < 4; ++ks) {
            const int kq = ks * 8;
            uint32_t af[4][4], bf[4][2];
#pragma unroll
            for (int mi = 0; mi < 4; ++mi) {
                int row = wm + mi * 16 + gID;
                af[mi][0] = sA[row * SAPADH + kq + tig];
                af[mi][1] = sA[(row + 8) * SAPADH + kq + tig];
                af[mi][2] = sA[row * SAPADH + kq + tig + 4];
                af[mi][3] = sA[(row + 8) * SAPADH + kq + tig + 4];
            }
#pragma unroll
            for (int ni = 0; ni < 4; ++ni) {
                int col = wn + ni * 8 + gID;
                bf[ni][0] = sB[col * SAPADH + kq + tig];
                bf[ni][1] = sB[col * SAPADH + kq + tig + 4];
            }
#pragma unroll
            for (int mi = 0; mi < 4; ++mi)
#pragma unroll
                for (int ni = 0; ni < 4; ++ni)
                    mma_f16(acc[mi][ni][0], acc[mi][ni][1], acc[mi][ni][2], acc[mi][ni][3],
                            af[mi][0], af[mi][1], af[mi][2], af[mi][3],
                            bf[ni][0], bf[ni][1]);
        }

        if (c + 2 < nch) issue(c + 2);
    }

    if (VMODE == 0) {
#pragma unroll
        for (int mi = 0; mi < 4; ++mi) {
            int row = m0 + wm + mi * 16 + gID;
#pragma unroll
            for (int ni = 0; ni < 4; ++ni) {
                int col = n0 + wn + ni * 8 + tig * 2;
                *reinterpret_cast<float2*>(C + (size_t)row * N + col) =
                    make_float2(acc[mi][ni][0], acc[mi][ni][1]);
                *reinterpret_cast<float2*>(C + (size_t)(row + 8) * N + col) =
                    make_float2(acc[mi][ni][2], acc[mi][ni][3]);
            }
        }
    } else {
#pragma unroll
        for (int mi = 0; mi < 4; ++mi) {
            int row = m0 + wm + mi * 16 + gID;
            int b0i = row >> 11, s0i = row & 2047;
            int b1i = (row + 8) >> 11, s1i = (row + 8) & 2047;
#pragma unroll
            for (int ni = 0; ni < 4; ++ni) {
                int col = n0 + wn + ni * 8 + tig * 2;
#pragma unroll
                for (int cc = 0; cc < 2; ++cc) {
                    int n = col + cc;
                    int kv = n >> 7, d = n & 127;
                    size_t base = ((size_t)(b0i * NKVH + kv) * HDIM + d) * SEQ;
                    Vt[base + s0i] = __float2half_rn(acc[mi][ni][cc]);
                    size_t base1 = ((size_t)(b1i * NKVH + kv) * HDIM + d) * SEQ;
                    Vt[base1 + s1i] = __float2half_rn(acc[mi][ni][cc + 2]);
                }
            }
        }
    }
}

__global__ __launch_bounds__(256, 2) void gemm_f16(
    const uint32_t* __restrict__ A, const uint32_t* __restrict__ B,
    float* __restrict__ C, int M, int N, int K)
{
    extern __shared__ uint32_t smem[];
    gemm_body_f16<0>(A, B, C, nullptr, M, N, K, blockIdx.x, blockIdx.y, smem);
}

__global__ __launch_bounds__(256, 2) void gemm_kv_f16(
    const uint32_t* __restrict__ A,
    const uint32_t* __restrict__ Wk, const uint32_t* __restrict__ Wv,
    float* __restrict__ Kout, __half* __restrict__ Vt,
    int M, int N, int K)
{
    extern __shared__ uint32_t smem[];
    if (blockIdx.z == 0)
        gemm_body_f16<0>(A, Wk, Kout, nullptr, M, N, K, blockIdx.x, blockIdx.y, smem);
    else
        gemm_body_f16<1>(A, Wv, nullptr, Vt, M, N, K, blockIdx.x, blockIdx.y, smem);
}

// ---------------------------------------------------------------------------
// RoPE: fp32 in, pre-scaled fp16 out.
// ---------------------------------------------------------------------------
__global__ void rope_kernel(const float* __restrict__ cosb,
                            const float* __restrict__ sinb)
{
    const int total = BATCH * SEQ * (NHEADS + NKVH) * 32;
    int idx = blockIdx.x * blockDim.x + threadIdx.x;
    if (idx >= total) return;
    int e    = idx & 31;
    int rest = idx >> 5;
    int slot = rest % (NHEADS + NKVH);
    int bs   = rest / (NHEADS + NKVH);
    int s    = bs % SEQ;

    const float2* cp = reinterpret_cast<const float2*>(cosb + s * HDIM);
    const float2* sp = reinterpret_cast<const float2*>(sinb + s * HDIM);
    float2 c0 = cp[e], c1 = cp[e + 32];
    float2 s0 = sp[e], s1 = sp[e + 32];

    const float2* p;
    uint32_t* o;
    float mult;
    if (slot < NHEADS) {
        p = reinterpret_cast<const float2*>(g_Q + (size_t)(bs * NHEADS + slot) * HDIM);
        o = g_Qh + (size_t)(bs * NHEADS + slot) * 64;
        mult = 0.08838834764831845f * 1.4426950408889634f;
    } else {
        p = reinterpret_cast<const float2*>(g_K + (size_t)(bs * NKVH + (slot - NHEADS)) * HDIM);
        o = g_Kh + (size_t)(bs * NKVH + (slot - NHEADS)) * 64;
        mult = 1.0f;
    }

    float2 x0 = p[e];
    float2 x1 = p[e + 32];
    float o0x = x0.x * c0.x - x1.x * s0.x;
    float o0y = x0.y * c0.y - x1.y * s0.y;
    float o1x = x1.x * c1.x + x0.x * s1.x;
    float o1y = x1.y * c1.y + x0.y * s1.y;
    o[e]      = pack2(o0x * mult, o0y * mult);
    o[e + 32] = pack2(o1x * mult, o1y * mult);
}

// ===========================================================================
// FP16 MMA flash attention: 2 heads x 32 queries per CTA (128 threads, 4 warps).
// warp w: head_local = w>>1, 16-row half = w&1. KV shared across the 2 heads.
// 3 CTAs/SM (reg-limited). (R12 configuration — best known.)
// ===========================================================================
constexpr int KSTRH = 68;
constexpr int VSTRH = 20;
constexpr int QSTRH = 68;
constexpr int PSTRH = 20;

constexpr int AKS0 = 0;
constexpr int AKS1 = AKS0 + 32 * KSTRH;
constexpr int AVS0 = AKS1 + 32 * KSTRH;
constexpr int AVS1 = AVS0 + 128 * VSTRH;
constexpr int AQS  = AVS1 + 128 * VSTRH;
constexpr int APS  = AQS + 64 * QSTRH;
constexpr int SMEM_ATTN = (APS + 4 * 16 * PSTRH) * 4;   // 60416 B

__global__ __launch_bounds__(128) void attn_f16_kernel()
{
    extern __shared__ uint32_t sm[];

    const int tid  = threadIdx.x;
    const int lane = tid & 31;
    const int wid  = tid >> 5;
    const int hl   = wid >> 1;
    const int sub  = wid & 1;
    const int g    = lane >> 2;
    const int t    = lane & 3;

    const int q0  = blockIdx.x * 32;
    const int hp  = blockIdx.y;
    const int kvh = hp >> 1;
    const int b   = blockIdx.z;
    const int h   = hp * 2 + hl;
    const int bS  = b * SEQ;
    const int qw  = q0 + sub * 16;

    const uint32_t sbase = (uint32_t)__cvta_generic_to_shared(sm);

    // ---- stage Q tiles for the 2 heads ----
#pragma unroll
    for (int i = tid; i < 1024; i += 128) {
        int ih = i >> 9;
        int r  = (i >> 4) & 31;
        int ch = i & 15;
        const uint32_t* src = g_Qh +
            ((size_t)(bS + q0 + r) * NHEADS + hp * 2 + ih) * 64 + ch * 4;
        cp16(sbase + (uint32_t)(AQS + (ih * 32 + r) * QSTRH + ch * 4) * 4, src);
    }
    asm volatile("cp.async.commit_group;");

    // ---- stage first K/V tile ----
    int jstart = q0 - (WIN - 1);
    if (jstart < 0) jstart = 0;
    jstart &= ~31;
    const int nt = (q0 + 32 - jstart) >> 5;

    auto stage_kv = [&](int j0, int buf) {
        const int ko = buf ? AKS1 : AKS0;
        const int vo = buf ? AVS1 : AVS0;
#pragma unroll
        for (int i = tid; i < 512; i += 128) {
            int r = i >> 4, ch = i & 15;
            const uint32_t* src = g_Kh + ((size_t)(bS + j0 + r) * NKVH + kvh) * 64 + ch * 4;
            cp16(sbase + (uint32_t)(ko + r * KSTRH + ch * 4) * 4, src);
        }
        const uint32_t* Vt = reinterpret_cast<const uint32_t*>(g_Vth) +
            ((size_t)(b * NKVH + kvh) * HDIM) * (SEQ / 2);
#pragma unroll
        for (int i = tid; i < 512; i += 128) {
            int d = i >> 2, ch = i & 3;
            const uint32_t* src = Vt + (size_t)d * (SEQ / 2) + (j0 >> 1) + ch * 4;
            cp16(sbase + (uint32_t)(vo + d * VSTRH + ch * 4) * 4, src);
        }
        asm volatile("cp.async.commit_group;");
    };

    stage_kv(jstart, 0);

    asm volatile("cp.async.wait_group 1;");
    __syncthreads();
    uint32_t qf[8][4];
#pragma unroll
    for (int kk = 0; kk < 8; ++kk) {
        int r0 = AQS + (hl * 32 + sub * 16 + g) * QSTRH + kk * 8 + t;
        qf[kk][0] = sm[r0];
        qf[kk][1] = sm[r0 + 8 * QSTRH];
        qf[kk][2] = sm[r0 + 4];
        qf[kk][3] = sm[r0 + 8 * QSTRH + 4];
    }

    uint32_t* Pw = &sm[APS + wid * 16 * PSTRH];

    float m0r = -1e30f, m1r = -1e30f, l0 = 0.f, l1 = 0.f;
    float oacc[16][4];
#pragma unroll
    for (int ni = 0; ni < 16; ++ni)
#pragma unroll
        for (int qd = 0; qd < 4; ++qd) oacc[ni][qd] = 0.f;

    for (int it = 0; it < nt; ++it) {
        const int j0 = jstart + it * 32;
        if (it + 1 < nt) {
            stage_kv(j0 + 32, (it + 1) & 1);
            asm volatile("cp.async.wait_group 1;");
        } else {
            asm volatile("cp.async.wait_group 0;");
        }
        __syncthreads();

        const bool active = (j0 <= qw + 15) && (qw - (j0 + 31) < WIN);
        if (active) {
            const uint32_t* Ks = &sm[(it & 1) ? AKS1 : AKS0];
            const uint32_t* Vs = &sm[(it & 1) ? AVS1 : AVS0];

            // ---- QK^T ----
            float sc[4][4];
#pragma unroll
            for (int ni = 0; ni < 4; ++ni)
#pragma unroll
                for (int qd = 0; qd < 4; ++qd) sc[ni][qd] = 0.f;

#pragma unroll
            for (int kk = 0; kk < 8; ++kk) {
#pragma unroll
                for (int ni = 0; ni < 4; ++ni) {
                    uint32_t b0 = Ks[(ni * 8 + g) * KSTRH + kk * 8 + t];
                    uint32_t b1 = Ks[(ni * 8 + g) * KSTRH + kk * 8 + t + 4];
                    mma_f16(sc[ni][0], sc[ni][1], sc[ni][2], sc[ni][3],
                            qf[kk][0], qf[kk][1], qf[kk][2], qf[kk][3], b0, b1);
                }
            }

            // ---- mask + row max ----
            const int r0 = qw + g;
            float tmax0 = -1e30f, tmax1 = -1e30f;
#pragma unroll
            for (int ni = 0; ni < 4; ++ni) {
                int col0 = j0 + ni * 8 + 2 * t;
#pragma unroll
                for (int cc = 0; cc < 2; ++cc) {
                    int col = col0 + cc;
                    int d0 = r0 - col;
                    int d1 = r0 + 8 - col;
                    if (!(d0 >= 0 && d0 < WIN)) sc[ni][cc]     = -1e30f;
                    if (!(d1 >= 0 && d1 < WIN)) sc[ni][cc + 2] = -1e30f;
                    tmax0 = fmaxf(tmax0, sc[ni][cc]);
                    tmax1 = fmaxf(tmax1, sc[ni][cc + 2]);
                }
            }
            tmax0 = fmaxf(tmax0, __shfl_xor_sync(0xffffffffu, tmax0, 1));
            tmax0 = fmaxf(tmax0, __shfl_xor_sync(0xffffffffu, tmax0, 2));
            tmax1 = fmaxf(tmax1, __shfl_xor_sync(0xffffffffu, tmax1, 1));
            tmax1 = fmaxf(tmax1, __shfl_xor_sync(0xffffffffu, tmax1, 2));

            float mn0 = fmaxf(m0r, tmax0);
            float mn1 = fmaxf(m1r, tmax1);
            float cor0 = ex2(m0r - mn0);
            float cor1 = ex2(m1r - mn1);
            m0r = mn0; m1r = mn1;

            float ps0 = 0.f, ps1 = 0.f;
#pragma unroll
            for (int ni = 0; ni < 4; ++ni) {
                float p00 = (sc[ni][0] > -1e29f) ? ex2(sc[ni][0] - mn0) : 0.f;
                float p01 = (sc[ni][1] > -1e29f) ? ex2(sc[ni][1] - mn0) : 0.f;
                float p10 = (sc[ni][2] > -1e29f) ? ex2(sc[ni][2] - mn1) : 0.f;
                float p11 = (sc[ni][3] > -1e29f) ? ex2(sc[ni][3] - mn1) : 0.f;
                ps0 += p00 + p01;
                ps1 += p10 + p11;
                Pw[g * PSTRH + ni * 4 + t]       = pack2(p00, p01);
                Pw[(g + 8) * PSTRH + ni * 4 + t] = pack2(p10, p11);
            }
            ps0 += __shfl_xor_sync(0xffffffffu, ps0, 1);
            ps0 += __shfl_xor_sync(0xffffffffu, ps0, 2);
            ps1 += __shfl_xor_sync(0xffffffffu, ps1, 1);
            ps1 += __shfl_xor_sync(0xffffffffu, ps1, 2);
            l0 = l0 * cor0 + ps0;
            l1 = l1 * cor1 + ps1;

#pragma unroll
            for (int ni = 0; ni < 16; ++ni) {
                oacc[ni][0] *= cor0; oacc[ni][1] *= cor0;
                oacc[ni][2] *= cor1; oacc[ni][3] *= cor1;
            }

            __syncwarp();

            // ---- PV: out += P[16x32] * V[32x128] ----
#pragma unroll
            for (int kc = 0; kc < 2; ++kc) {
                uint32_t a0 = Pw[g * PSTRH + kc * 8 + t];
                uint32_t a1 = Pw[(g + 8) * PSTRH + kc * 8 + t];
                uint32_t a2 = Pw[g * PSTRH + kc * 8 + t + 4];
                uint32_t a3 = Pw[(g + 8) * PSTRH + kc * 8 + t + 4];
#pragma unroll
                for (int ni = 0; ni < 16; ++ni) {
                    uint32_t b0 = Vs[(ni * 8 + g) * VSTRH + kc * 8 + t];
                    uint32_t b1 = Vs[(ni * 8 + g) * VSTRH + kc * 8 + t + 4];
                    mma_f16(oacc[ni][0], oacc[ni][1], oacc[ni][2], oacc[ni][3],
                            a0, a1, a2, a3, b0, b1);
                }
            }
            __syncwarp();
        }
        __syncthreads();
    }

    // ---- normalize + store half2 for O-projection ----
    float inv0 = 1.f / l0;
    float inv1 = 1.f / l1;
    uint32_t* Ot  = g_AOh + ((size_t)(bS + qw + g) * NHEADS + h) * 64;
    uint32_t* Ot8 = Ot + (size_t)8 * NHEADS * 64;
#pragma unroll
    for (int ni = 0; ni < 16; ++ni) {
        Ot[ni * 4 + t]  = pack2(oacc[ni][0] * inv0, oacc[ni][1] * inv0);
        Ot8[ni * 4 + t] = pack2(oacc[ni][2] * inv1, oacc[ni][3] * inv1);
    }
}

// ---------------------------------------------------------------------------
// Launch
// ---------------------------------------------------------------------------
extern "C" void kernel_launch(void* const* d_in, const int* in_sizes, int n_in,
                              void* d_out, int out_size)
{
    const float* x    = (const float*)d_in[0];
    const float* cosb = (const float*)d_in[1];
    const float* sinb = (const float*)d_in[2];
    const float* Wq   = (const float*)d_in[3];
    const float* Wk   = (const float*)d_in[4];
    const float* Wv   = (const float*)d_in[5];
    const float* Wo   = (const float*)d_in[6];
    float* out = (float*)d_out;

    float *Q, *K;
    uint32_t *xh, *Wqh, *Wkh, *Wvh, *Woh, *AOh;
    __half* Vth;
    cudaGetSymbolAddress((void**)&Q,   g_Q);
    cudaGetSymbolAddress((void**)&K,   g_K);
    cudaGetSymbolAddress((void**)&xh,  g_xh);
    cudaGetSymbolAddress((void**)&Wqh, g_Wqh);
    cudaGetSymbolAddress((void**)&Wkh, g_Wkh);
    cudaGetSymbolAddress((void**)&Wvh, g_Wvh);
    cudaGetSymbolAddress((void**)&Woh, g_Woh);
    cudaGetSymbolAddress((void**)&AOh, g_AOh);
    cudaGetSymbolAddress((void**)&Vth, g_Vth);

    static bool attr_done = false;
    if (!attr_done) {
        cudaFuncSetAttribute(gemm_f16,    cudaFuncAttributeMaxDynamicSharedMemorySize, SMEM_GEMM);
        cudaFuncSetAttribute(gemm_kv_f16, cudaFuncAttributeMaxDynamicSharedMemorySize, SMEM_GEMM);
        cudaFuncSetAttribute(attn_f16_kernel, cudaFuncAttributeMaxDynamicSharedMemorySize, SMEM_ATTN);
        attr_done = true;
    }

    const int M = BATCH * SEQ;

    // x convert (single), then paired weight converts (grid.z selects)
    {
        int n4x = BATCH * SEQ * EMB / 4;
        cvt_h_kernel<<<(n4x + 255) / 256, 256>>>(
            reinterpret_cast<const float4*>(x), reinterpret_cast<uint2*>(xh), n4x);

        int n4w = EMB * EMB / 4;            // Wq / Wo (same size)
        cvt_h2_kernel<<<dim3((n4w + 255) / 256, 1, 2), 256>>>(
            reinterpret_cast<const float4*>(Wq), reinterpret_cast<uint2*>(Wqh),
            reinterpret_cast<const float4*>(Wo), reinterpret_cast<uint2*>(Woh), n4w);

        int n4kv = NKVH * HDIM * EMB / 4;   // Wk / Wv (same size)
        cvt_h2_kernel<<<dim3((n4kv + 255) / 256, 1, 2), 256>>>(
            reinterpret_cast<const float4*>(Wk), reinterpret_cast<uint2*>(Wkh),
            reinterpret_cast<const float4*>(Wv), reinterpret_cast<uint2*>(Wvh), n4kv);
    }

    // Q projection (fp32 out, rope converts)
    gemm_f16<<<dim3(EMB / 128, M / 128), 256, SMEM_GEMM>>>(xh, Wqh, Q, M, NHEADS * HDIM, EMB);
    // K (fp32 out) + V (fp16 transposed out) fused
    gemm_kv_f16<<<dim3((NKVH * HDIM) / 128, M / 128, 2), 256, SMEM_GEMM>>>(
        xh, Wkh, Wvh, K, Vth, M, NKVH * HDIM, EMB);

    {
        int total = BATCH * SEQ * (NHEADS + NKVH) * 32;
        rope_kernel<<<(total + 255) / 256, 256>>>(cosb, sinb);
    }

    // 2 heads per CTA, 128 threads (R12 best config)
    attn_f16_kernel<<<dim3(SEQ / 32, NHEADS / 2, BATCH), 128, SMEM_ATTN>>>();

    // Output projection (A = attention output fp16)
    gemm_f16<<<dim3(EMB / 128, M / 128), 256, SMEM_GEMM>>>(AOh, Woh, out, M, EMB, EMB);
}

// round 15
// speedup vs baseline: 1.2539x; 1.0921x over previous
#include <cuda_runtime.h>
#include <cuda_fp16.h>
#include <cstdint>
#include <math.h>

// Problem constants
constexpr int BATCH  = 2;
constexpr int SEQ    = 2048;
constexpr int EMB    = 2048;
constexpr int NHEADS = 16;
constexpr int NKVH   = 4;
constexpr int HDIM   = 128;
constexpr int WIN    = 1024;
constexpr int GQA    = NHEADS / NKVH;

// fp32 scratch (pre-rope Q/K)
__device__ __align__(16) float g_Q [BATCH * SEQ * NHEADS * HDIM];
__device__ __align__(16) float g_K [BATCH * SEQ * NKVH   * HDIM];
// fp16 (half2-in-u32) scratch
__device__ __align__(16) uint32_t g_xh [BATCH * SEQ * (EMB / 2)];
__device__ __align__(16) uint32_t g_Wqh[EMB * (EMB / 2)];
__device__ __align__(16) uint32_t g_Wkh[NKVH * HDIM * (EMB / 2)];
__device__ __align__(16) uint32_t g_Wvh[NKVH * HDIM * (EMB / 2)];
__device__ __align__(16) uint32_t g_Woh[EMB * (EMB / 2)];
__device__ __align__(16) uint32_t g_Qh [BATCH * SEQ * NHEADS * (HDIM / 2)];  // pre-scaled
__device__ __align__(16) uint32_t g_Kh [BATCH * SEQ * NKVH   * (HDIM / 2)];
__device__ __align__(16) __half   g_Vth[BATCH * NKVH * HDIM * SEQ];          // [b][kvh][d][s]
__device__ __align__(16) uint32_t g_AOh[BATCH * SEQ * (EMB / 2)];

__device__ __forceinline__ uint32_t pack2(float lo, float hi) {
    uint32_t r;
    asm("cvt.rn.f16x2.f32 %0, %1, %2;" : "=r"(r) : "f"(hi), "f"(lo));
    return r;
}
__device__ __forceinline__ float ex2(float x) {
    float r;
    asm("ex2.approx.f32 %0, %1;" : "=f"(r) : "f"(x));
    return r;
}
__device__ __forceinline__ void mma_f16(
    float& d0, float& d1, float& d2, float& d3,
    uint32_t a0, uint32_t a1, uint32_t a2, uint32_t a3,
    uint32_t b0, uint32_t b1)
{
    asm volatile(
        "mma.sync.aligned.m16n8k16.row.col.f32.f16.f16.f32 "
        "{%0,%1,%2,%3}, {%4,%5,%6,%7}, {%8,%9}, {%0,%1,%2,%3};"
        : "+f"(d0), "+f"(d1), "+f"(d2), "+f"(d3)
        : "r"(a0), "r"(a1), "r"(a2), "r"(a3), "r"(b0), "r"(b1));
}
__device__ __forceinline__ void cp16(uint32_t saddr, const void* gptr) {
    asm volatile("cp.async.cg.shared.global [%0], [%1], 16;"
                 :: "r"(saddr), "l"(gptr));
}
__device__ __forceinline__ void ldsm4(uint32_t& r0, uint32_t& r1,
                                      uint32_t& r2, uint32_t& r3, uint32_t saddr)
{
    asm volatile("ldmatrix.sync.aligned.m8n8.x4.shared.b16 {%0,%1,%2,%3}, [%4];"
        : "=r"(r0), "=r"(r1), "=r"(r2), "=r"(r3) : "r"(saddr));
}

// ---------------------------------------------------------------------------
// fp32 -> fp16x2 bulk convert (single tensor, and paired via grid.z)
// ---------------------------------------------------------------------------
__global__ void cvt_h_kernel(const float4* __restrict__ src,
                             uint2* __restrict__ dst, int n4)
{
    int i = blockIdx.x * blockDim.x + threadIdx.x;
    if (i >= n4) return;
    float4 v = src[i];
    dst[i] = make_uint2(pack2(v.x, v.y), pack2(v.z, v.w));
}

__global__ void cvt_h2_kernel(const float4* __restrict__ s0, uint2* __restrict__ d0,
                              const float4* __restrict__ s1, uint2* __restrict__ d1,
                              int n4)
{
    int i = blockIdx.x * blockDim.x + threadIdx.x;
    if (i >= n4) return;
    const float4* s = blockIdx.z ? s1 : s0;
    uint2* d        = blockIdx.z ? d1 : d0;
    float4 v = s[i];
    d[i] = make_uint2(pack2(v.x, v.y), pack2(v.z, v.w));
}

// ===========================================================================
// FP16 GEMM (NT): C[M,N] = A[M,K] * B[N,K]^T ; 128x128 tile, BK=64 halfs,
// 3-stage cp.async. R15 change: ldmatrix.x4 fragment loads (4x fewer LDS ops).
// VMODE=1: write C as fp16 transposed into Vt[b][kvh][d][s].
// ===========================================================================
constexpr int SAPADH = 36;
constexpr int TILE_H = 128 * SAPADH;
constexpr int NSTG = 3;
constexpr int SMEM_GEMM = NSTG * 2 * TILE_H * 4;

template<int VMODE>
__device__ __forceinline__ void gemm_body_f16(
    const uint32_t* __restrict__ A, const uint32_t* __restrict__ B,
    float* __restrict__ C, __half* __restrict__ Vt,
    int M, int N, int K, int bx, int by, uint32_t* smem)
{
    const int K2 = K / 2;
    const int tid  = threadIdx.x;
    const int lane = tid & 31;
    const int wid  = tid >> 5;
    const int m0 = by * 128;
    const int n0 = bx * 128;

    const int wm  = (wid >> 2) * 64;
    const int wn  = (wid & 3) * 32;
    const int gID = lane >> 2;
    const int tig = lane & 3;

    const int lr0 = tid >> 3;
    const int lc4 = tid & 7;

    // ldmatrix lane address components (verified conflict-free with stride 36)
    const int laneA_row = wm + (lane & 15);
    const int laneA_chk = (lane >> 4) * 4;
    const int laneB_row = wn + ((lane >> 4) & 1) * 8 + (lane & 7);
    const int laneB_chk = ((lane >> 3) & 1) * 4;

    const uint32_t* Abase = A + (size_t)(m0 + lr0) * K2 + lc4 * 4;
    const uint32_t* Bbase = B + (size_t)(n0 + lr0) * K2 + lc4 * 4;
    const uint32_t sbase = (uint32_t)__cvta_generic_to_shared(smem);

    float acc[4][4][4];
#pragma unroll
    for (int mi = 0; mi < 4; ++mi)
#pragma unroll
        for (int ni = 0; ni < 4; ++ni)
#pragma unroll
            for (int q = 0; q < 4; ++q) acc[mi][ni][q] = 0.f;

    const int nch = K / 64;

    auto issue = [&](int c) {
        const uint32_t st = sbase + (uint32_t)((c % NSTG) * 2 * TILE_H) * 4;
        const int kb = c * 32;
#pragma unroll
        for (int j = 0; j < 4; ++j) {
            int r = lr0 + 32 * j;
            cp16(st + (uint32_t)(r * SAPADH + lc4 * 4) * 4,
                 Abase + (size_t)(32 * j) * K2 + kb);
            cp16(st + (uint32_t)(TILE_H + r * SAPADH + lc4 * 4) * 4,
                 Bbase + (size_t)(32 * j) * K2 + kb);
        }
        asm volatile("cp.async.commit_group;");
    };

    issue(0);
    issue(1);

    for (int c = 0; c < nch; ++c) {
        if (c + 1 < nch) asm volatile("cp.async.wait_group 1;");
        else             asm volatile("cp.async.wait_group 0;");
        __syncthreads();

        const uint32_t stg = sbase + (uint32_t)((c % NSTG) * 2 * TILE_H) * 4;
        const uint32_t aA = stg + (uint32_t)(laneA_row * SAPADH + laneA_chk) * 4;
        const uint32_t aB = stg + (uint32_t)(TILE_H + laneB_row * SAPADH + laneB_chk) * 4;

#pragma unroll
        for (int ks = 0; ks < 4; ++ks) {
            uint32_t af[4][4], bf[4][2];
            ldsm4(af[0][0], af[0][1], af[0][2], af[0][3], aA + ks * 32);
            ldsm4(af[1][0], af[1][1], af[1][2], af[1][3], aA + 16 * SAPADH * 4 + ks * 32);
            ldsm4(af[2][0], af[2][1], af[2][2], af[2][3], aA + 32 * SAPADH * 4 + ks * 32);
            ldsm4(af[3][0], af[3][1], af[3][2], af[3][3], aA + 48 * SAPADH * 4 + ks * 32);
            ldsm4(bf[0][0], bf[0][1], bf[1][0], bf[1][1], aB + ks * 32);
            ldsm4(bf[2][0], bf[2][1], bf[3][0], bf[3][1], aB + 16 * SAPADH * 4 + ks * 32);
#pragma unroll
            for (int mi = 0; mi < 4; ++mi)
#pragma unroll
                for (int ni = 0; ni < 4; ++ni)
                    mma_f16(acc[mi][ni][0], acc[mi][ni][1], acc[mi][ni][2], acc[mi][ni][3],
                            af[mi][0], af[mi][1], af[mi][2], af[mi][3],
                            bf[ni][0], bf[ni][1]);
        }

        if (c + 2 < nch) issue(c + 2);
    }

    if (VMODE == 0) {
#pragma unroll
        for (int mi = 0; mi < 4; ++mi) {
            int row = m0 + wm + mi * 16 + gID;
#pragma unroll
            for (int ni = 0; ni < 4; ++ni) {
                int col = n0 + wn + ni * 8 + tig * 2;
                *reinterpret_cast<float2*>(C + (size_t)row * N + col) =
                    make_float2(acc[mi][ni][0], acc[mi][ni][1]);
                *reinterpret_cast<float2*>(C + (size_t)(row + 8) * N + col) =
                    make_float2(acc[mi][ni][2], acc[mi][ni][3]);
            }
        }
    } else {
#pragma unroll
        for (int mi = 0; mi < 4; ++mi) {
            int row = m0 + wm + mi * 16 + gID;
            int b0i = row >> 11, s0i = row & 2047;
            int b1i = (row + 8) >> 11, s1i = (row + 8) & 2047;
#pragma unroll
            for (int ni = 0; ni < 4; ++ni) {
                int col = n0 + wn + ni * 8 + tig * 2;
#pragma unroll
                for (int cc = 0; cc < 2; ++cc) {
                    int n = col + cc;
                    int kv = n >> 7, d = n & 127;
                    size_t base = ((size_t)(b0i * NKVH + kv) * HDIM + d) * SEQ;
                    Vt[base + s0i] = __float2half_rn(acc[mi][ni][cc]);
                    size_t base1 = ((size_t)(b1i * NKVH + kv) * HDIM + d) * SEQ;
                    Vt[base1 + s1i] = __float2half_rn(acc[mi][ni][cc + 2]);
                }
            }
        }
    }
}

__global__ __launch_bounds__(256, 2) void gemm_f16(
    const uint32_t* __restrict__ A, const uint32_t* __restrict__ B,
    float* __restrict__ C, int M, int N, int K)
{
    extern __shared__ uint32_t smem[];
    gemm_body_f16<0>(A, B, C, nullptr, M, N, K, blockIdx.x, blockIdx.y, smem);
}

__global__ __launch_bounds__(256, 2) void gemm_kv_f16(
    const uint32_t* __restrict__ A,
    const uint32_t* __restrict__ Wk, const uint32_t* __restrict__ Wv,
    float* __restrict__ Kout, __half* __restrict__ Vt,
    int M, int N, int K)
{
    extern __shared__ uint32_t smem[];
    if (blockIdx.z == 0)
        gemm_body_f16<0>(A, Wk, Kout, nullptr, M, N, K, blockIdx.x, blockIdx.y, smem);
    else
        gemm_body_f16<1>(A, Wv, nullptr, Vt, M, N, K, blockIdx.x, blockIdx.y, smem);
}

// ---------------------------------------------------------------------------
// RoPE: fp32 in, pre-scaled fp16 out.
// ---------------------------------------------------------------------------
__global__ void rope_kernel(const float* __restrict__ cosb,
                            const float* __restrict__ sinb)
{
    const int total = BATCH * SEQ * (NHEADS + NKVH) * 32;
    int idx = blockIdx.x * blockDim.x + threadIdx.x;
    if (idx >= total) return;
    int e    = idx & 31;
    int rest = idx >> 5;
    int slot = rest % (NHEADS + NKVH);
    int bs   = rest / (NHEADS + NKVH);
    int s    = bs % SEQ;

    const float2* cp = reinterpret_cast<const float2*>(cosb + s * HDIM);
    const float2* sp = reinterpret_cast<const float2*>(sinb + s * HDIM);
    float2 c0 = cp[e], c1 = cp[e + 32];
    float2 s0 = sp[e], s1 = sp[e + 32];

    const float2* p;
    uint32_t* o;
    float mult;
    if (slot < NHEADS) {
        p = reinterpret_cast<const float2*>(g_Q + (size_t)(bs * NHEADS + slot) * HDIM);
        o = g_Qh + (size_t)(bs * NHEADS + slot) * 64;
        mult = 0.08838834764831845f * 1.4426950408889634f;
    } else {
        p = reinterpret_cast<const float2*>(g_K + (size_t)(bs * NKVH + (slot - NHEADS)) * HDIM);
        o = g_Kh + (size_t)(bs * NKVH + (slot - NHEADS)) * 64;
        mult = 1.0f;
    }

    float2 x0 = p[e];
    float2 x1 = p[e + 32];
    float o0x = x0.x * c0.x - x1.x * s0.x;
    float o0y = x0.y * c0.y - x1.y * s0.y;
    float o1x = x1.x * c1.x + x0.x * s1.x;
    float o1y = x1.y * c1.y + x0.y * s1.y;
    o[e]      = pack2(o0x * mult, o0y * mult);
    o[e + 32] = pack2(o1x * mult, o1y * mult);
}

// ===========================================================================
// FP16 MMA flash attention: 2 heads x 32 queries per CTA (128 threads, 4 warps).
// (R12/R14 configuration — best known; unchanged.)
// ===========================================================================
constexpr int KSTRH = 68;
constexpr int VSTRH = 20;
constexpr int QSTRH = 68;
constexpr int PSTRH = 20;

constexpr int AKS0 = 0;
constexpr int AKS1 = AKS0 + 32 * KSTRH;
constexpr int AVS0 = AKS1 + 32 * KSTRH;
constexpr int AVS1 = AVS0 + 128 * VSTRH;
constexpr int AQS  = AVS1 + 128 * VSTRH;
constexpr int APS  = AQS + 64 * QSTRH;
constexpr int SMEM_ATTN = (APS + 4 * 16 * PSTRH) * 4;   // 60416 B

__global__ __launch_bounds__(128) void attn_f16_kernel()
{
    extern __shared__ uint32_t sm[];

    const int tid  = threadIdx.x;
    const int lane = tid & 31;
    const int wid  = tid >> 5;
    const int hl   = wid >> 1;
    const int sub  = wid & 1;
    const int g    = lane >> 2;
    const int t    = lane & 3;

    const int q0  = blockIdx.x * 32;
    const int hp  = blockIdx.y;
    const int kvh = hp >> 1;
    const int b   = blockIdx.z;
    const int h   = hp * 2 + hl;
    const int bS  = b * SEQ;
    const int qw  = q0 + sub * 16;

    const uint32_t sbase = (uint32_t)__cvta_generic_to_shared(sm);

    // ---- stage Q tiles for the 2 heads ----
#pragma unroll
    for (int i = tid; i < 1024; i += 128) {
        int ih = i >> 9;
        int r  = (i >> 4) & 31;
        int ch = i & 15;
        const uint32_t* src = g_Qh +
            ((size_t)(bS + q0 + r) * NHEADS + hp * 2 + ih) * 64 + ch * 4;
        cp16(sbase + (uint32_t)(AQS + (ih * 32 + r) * QSTRH + ch * 4) * 4, src);
    }
    asm volatile("cp.async.commit_group;");

    // ---- stage first K/V tile ----
    int jstart = q0 - (WIN - 1);
    if (jstart < 0) jstart = 0;
    jstart &= ~31;
    const int nt = (q0 + 32 - jstart) >> 5;

    auto stage_kv = [&](int j0, int buf) {
        const int ko = buf ? AKS1 : AKS0;
        const int vo = buf ? AVS1 : AVS0;
#pragma unroll
        for (int i = tid; i < 512; i += 128) {
            int r = i >> 4, ch = i & 15;
            const uint32_t* src = g_Kh + ((size_t)(bS + j0 + r) * NKVH + kvh) * 64 + ch * 4;
            cp16(sbase + (uint32_t)(ko + r * KSTRH + ch * 4) * 4, src);
        }
        const uint32_t* Vt = reinterpret_cast<const uint32_t*>(g_Vth) +
            ((size_t)(b * NKVH + kvh) * HDIM) * (SEQ / 2);
#pragma unroll
        for (int i = tid; i < 512; i += 128) {
            int d = i >> 2, ch = i & 3;
            const uint32_t* src = Vt + (size_t)d * (SEQ / 2) + (j0 >> 1) + ch * 4;
            cp16(sbase + (uint32_t)(vo + d * VSTRH + ch * 4) * 4, src);
        }
        asm volatile("cp.async.commit_group;");
    };

    stage_kv(jstart, 0);

    asm volatile("cp.async.wait_group 1;");
    __syncthreads();
    uint32_t qf[8][4];
#pragma unroll
    for (int kk = 0; kk < 8; ++kk) {
        int r0 = AQS + (hl * 32 + sub * 16 + g) * QSTRH + kk * 8 + t;
        qf[kk][0] = sm[r0];
        qf[kk][1] = sm[r0 + 8 * QSTRH];
        qf[kk][2] = sm[r0 + 4];
        qf[kk][3] = sm[r0 + 8 * QSTRH + 4];
    }

    uint32_t* Pw = &sm[APS + wid * 16 * PSTRH];

    float m0r = -1e30f, m1r = -1e30f, l0 = 0.f, l1 = 0.f;
    float oacc[16][4];
#pragma unroll
    for (int ni = 0; ni < 16; ++ni)
#pragma unroll
        for (int qd = 0; qd < 4; ++qd) oacc[ni][qd] = 0.f;

    for (int it = 0; it < nt; ++it) {
        const int j0 = jstart + it * 32;
        if (it + 1 < nt) {
            stage_kv(j0 + 32, (it + 1) & 1);
            asm volatile("cp.async.wait_group 1;");
        } else {
            asm volatile("cp.async.wait_group 0;");
        }
        __syncthreads();

        const bool active = (j0 <= qw + 15) && (qw - (j0 + 31) < WIN);
        if (active) {
            const uint32_t* Ks = &sm[(it & 1) ? AKS1 : AKS0];
            const uint32_t* Vs = &sm[(it & 1) ? AVS1 : AVS0];

            // ---- QK^T ----
            float sc[4][4];
#pragma unroll
            for (int ni = 0; ni < 4; ++ni)
#pragma unroll
                for (int qd = 0; qd < 4; ++qd) sc[ni][qd] = 0.f;

#pragma unroll
            for (int kk = 0; kk < 8; ++kk) {
#pragma unroll
                for (int ni = 0; ni < 4; ++ni) {
                    uint32_t b0 = Ks[(ni * 8 + g) * KSTRH + kk * 8 + t];
                    uint32_t b1 = Ks[(ni * 8 + g) * KSTRH + kk * 8 + t + 4];
                    mma_f16(sc[ni][0], sc[ni][1], sc[ni][2], sc[ni][3],
                            qf[kk][0], qf[kk][1], qf[kk][2], qf[kk][3], b0, b1);
                }
            }

            // ---- mask + row max ----
            const int r0 = qw + g;
            float tmax0 = -1e30f, tmax1 = -1e30f;
#pragma unroll
            for (int ni = 0; ni < 4; ++ni) {
                int col0 = j0 + ni * 8 + 2 * t;
#pragma unroll
                for (int cc = 0; cc < 2; ++cc) {
                    int col = col0 + cc;
                    int d0 = r0 - col;
                    int d1 = r0 + 8 - col;
                    if (!(d0 >= 0 && d0 < WIN)) sc[ni][cc]     = -1e30f;
                    if (!(d1 >= 0 && d1 < WIN)) sc[ni][cc + 2] = -1e30f;
                    tmax0 = fmaxf(tmax0, sc[ni][cc]);
                    tmax1 = fmaxf(tmax1, sc[ni][cc + 2]);
                }
            }
            tmax0 = fmaxf(tmax0, __shfl_xor_sync(0xffffffffu, tmax0, 1));
            tmax0 = fmaxf(tmax0, __shfl_xor_sync(0xffffffffu, tmax0, 2));
            tmax1 = fmaxf(tmax1, __shfl_xor_sync(0xffffffffu, tmax1, 1));
            tmax1 = fmaxf(tmax1, __shfl_xor_sync(0xffffffffu, tmax1, 2));

            float mn0 = fmaxf(m0r, tmax0);
            float mn1 = fmaxf(m1r, tmax1);
            float cor0 = ex2(m0r - mn0);
            float cor1 = ex2(m1r - mn1);
            m0r = mn0; m1r = mn1;

            float ps0 = 0.f, ps1 = 0.f;
#pragma unroll
            for (int ni = 0; ni < 4; ++ni) {
                float p00 = (sc[ni][0] > -1e29f) ? ex2(sc[ni][0] - mn0) : 0.f;
                float p01 = (sc[ni][1] > -1e29f) ? ex2(sc[ni][1] - mn0) : 0.f;
                float p10 = (sc[ni][2] > -1e29f) ? ex2(sc[ni][2] - mn1) : 0.f;
                float p11 = (sc[ni][3] > -1e29f) ? ex2(sc[ni][3] - mn1) : 0.f;
                ps0 += p00 + p01;
                ps1 += p10 + p11;
                Pw[g * PSTRH + ni * 4 + t]       = pack2(p00, p01);
                Pw[(g + 8) * PSTRH + ni * 4 + t] = pack2(p10, p11);
            }
            ps0 += __shfl_xor_sync(0xffffffffu, ps0, 1);
            ps0 += __shfl_xor_sync(0xffffffffu, ps0, 2);
            ps1 += __shfl_xor_sync(0xffffffffu, ps1, 1);
            ps1 += __shfl_xor_sync(0xffffffffu, ps1, 2);
            l0 = l0 * cor0 + ps0;
            l1 = l1 * cor1 + ps1;

#pragma unroll
            for (int ni = 0; ni < 16; ++ni) {
                oacc[ni][0] *= cor0; oacc[ni][1] *= cor0;
                oacc[ni][2] *= cor1; oacc[ni][3] *= cor1;
            }

            __syncwarp();

            // ---- PV: out += P[16x32] * V[32x128] ----
#pragma unroll
            for (int kc = 0; kc < 2; ++kc) {
                uint32_t a0 = Pw[g * PSTRH + kc * 8 + t];
                uint32_t a1 = Pw[(g + 8) * PSTRH + kc * 8 + t];
                uint32_t a2 = Pw[g * PSTRH + kc * 8 + t + 4];
                uint32_t a3 = Pw[(g + 8) * PSTRH + kc * 8 + t + 4];
#pragma unroll
                for (int ni = 0; ni < 16; ++ni) {
                    uint32_t b0 = Vs[(ni * 8 + g) * VSTRH + kc * 8 + t];
                    uint32_t b1 = Vs[(ni * 8 + g) * VSTRH + kc * 8 + t + 4];
                    mma_f16(oacc[ni][0], oacc[ni][1], oacc[ni][2], oacc[ni][3],
                            a0, a1, a2, a3, b0, b1);
                }
            }
            __syncwarp();
        }
        __syncthreads();
    }

    // ---- normalize + store half2 for O-projection ----
    float inv0 = 1.f / l0;
    float inv1 = 1.f / l1;
    uint32_t* Ot  = g_AOh + ((size_t)(bS + qw + g) * NHEADS + h) * 64;
    uint32_t* Ot8 = Ot + (size_t)8 * NHEADS * 64;
#pragma unroll
    for (int ni = 0; ni < 16; ++ni) {
        Ot[ni * 4 + t]  = pack2(oacc[ni][0] * inv0, oacc[ni][1] * inv0);
        Ot8[ni * 4 + t] = pack2(oacc[ni][2] * inv1, oacc[ni][3] * inv1);
    }
}

// ---------------------------------------------------------------------------
// Launch
// ---------------------------------------------------------------------------
extern "C" void kernel_launch(void* const* d_in, const int* in_sizes, int n_in,
                              void* d_out, int out_size)
{
    const float* x    = (const float*)d_in[0];
    const float* cosb = (const float*)d_in[1];
    const float* sinb = (const float*)d_in[2];
    const float* Wq   = (const float*)d_in[3];
    const float* Wk   = (const float*)d_in[4];
    const float* Wv   = (const float*)d_in[5];
    const float* Wo   = (const float*)d_in[6];
    float* out = (float*)d_out;

    float *Q, *K;
    uint32_t *xh, *Wqh, *Wkh, *Wvh, *Woh, *AOh;
    __half* Vth;
    cudaGetSymbolAddress((void**)&Q,   g_Q);
    cudaGetSymbolAddress((void**)&K,   g_K);
    cudaGetSymbolAddress((void**)&xh,  g_xh);
    cudaGetSymbolAddress((void**)&Wqh, g_Wqh);
    cudaGetSymbolAddress((void**)&Wkh, g_Wkh);
    cudaGetSymbolAddress((void**)&Wvh, g_Wvh);
    cudaGetSymbolAddress((void**)&Woh, g_Woh);
    cudaGetSymbolAddress((void**)&AOh, g_AOh);
    cudaGetSymbolAddress((void**)&Vth, g_Vth);

    static bool attr_done = false;
    if (!attr_done) {
        cudaFuncSetAttribute(gemm_f16,    cudaFuncAttributeMaxDynamicSharedMemorySize, SMEM_GEMM);
        cudaFuncSetAttribute(gemm_kv_f16, cudaFuncAttributeMaxDynamicSharedMemorySize, SMEM_GEMM);
        cudaFuncSetAttribute(attn_f16_kernel, cudaFuncAttributeMaxDynamicSharedMemorySize, SMEM_ATTN);
        attr_done = true;
    }

    const int M = BATCH * SEQ;

    // x convert (single), then paired weight converts (grid.z selects)
    {
        int n4x = BATCH * SEQ * EMB / 4;
        cvt_h_kernel<<<(n4x + 255) / 256, 256>>>(
            reinterpret_cast<const float4*>(x), reinterpret_cast<uint2*>(xh), n4x);

        int n4w = EMB * EMB / 4;            // Wq / Wo (same size)
        cvt_h2_kernel<<<dim3((n4w + 255) / 256, 1, 2), 256>>>(
            reinterpret_cast<const float4*>(Wq), reinterpret_cast<uint2*>(Wqh),
            reinterpret_cast<const float4*>(Wo), reinterpret_cast<uint2*>(Woh), n4w);

        int n4kv = NKVH * HDIM * EMB / 4;   // Wk / Wv (same size)
        cvt_h2_kernel<<<dim3((n4kv + 255) / 256, 1, 2), 256>>>(
            reinterpret_cast<const float4*>(Wk), reinterpret_cast<uint2*>(Wkh),
            reinterpret_cast<const float4*>(Wv), reinterpret_cast<uint2*>(Wvh), n4kv);
    }

    // Q projection (fp32 out, rope converts)
    gemm_f16<<<dim3(EMB / 128, M / 128), 256, SMEM_GEMM>>>(xh, Wqh, Q, M, NHEADS * HDIM, EMB);
    // K (fp32 out) + V (fp16 transposed out) fused
    gemm_kv_f16<<<dim3((NKVH * HDIM) / 128, M / 128, 2), 256, SMEM_GEMM>>>(
        xh, Wkh, Wvh, K, Vth, M, NKVH * HDIM, EMB);

    {
        int total = BATCH * SEQ * (NHEADS + NKVH) * 32;
        rope_kernel<<<(total + 255) / 256, 256>>>(cosb, sinb);
    }

    // 2 heads per CTA, 128 threads (best attention config)
    attn_f16_kernel<<<dim3(SEQ / 32, NHEADS / 2, BATCH), 128, SMEM_ATTN>>>();

    // Output projection (A = attention output fp16)
    gemm_f16<<<dim3(EMB / 128, M / 128), 256, SMEM_GEMM>>>(AOh, Woh, out, M, EMB, EMB);
}

// round 16
// speedup vs baseline: 1.3119x; 1.0463x over previous
#include <cuda_runtime.h>
#include <cuda_fp16.h>
#include <cstdint>
#include <math.h>

// Problem constants
constexpr int BATCH  = 2;
constexpr int SEQ    = 2048;
constexpr int EMB    = 2048;
constexpr int NHEADS = 16;
constexpr int NKVH   = 4;
constexpr int HDIM   = 128;
constexpr int WIN    = 1024;
constexpr int GQA    = NHEADS / NKVH;

// fp32 scratch (pre-rope Q/K)
__device__ __align__(16) float g_Q [BATCH * SEQ * NHEADS * HDIM];
__device__ __align__(16) float g_K [BATCH * SEQ * NKVH   * HDIM];
// fp16 (half2-in-u32) scratch
__device__ __align__(16) uint32_t g_xh [BATCH * SEQ * (EMB / 2)];
__device__ __align__(16) uint32_t g_Wqh[EMB * (EMB / 2)];
__device__ __align__(16) uint32_t g_Wkh[NKVH * HDIM * (EMB / 2)];
__device__ __align__(16) uint32_t g_Wvh[NKVH * HDIM * (EMB / 2)];
__device__ __align__(16) uint32_t g_Woh[EMB * (EMB / 2)];
__device__ __align__(16) uint32_t g_Qh [BATCH * SEQ * NHEADS * (HDIM / 2)];  // pre-scaled
__device__ __align__(16) uint32_t g_Kh [BATCH * SEQ * NKVH   * (HDIM / 2)];
__device__ __align__(16) __half   g_Vth[BATCH * NKVH * HDIM * SEQ];          // [b][kvh][d][s]
__device__ __align__(16) uint32_t g_AOh[BATCH * SEQ * (EMB / 2)];

__device__ __forceinline__ uint32_t pack2(float lo, float hi) {
    uint32_t r;
    asm("cvt.rn.f16x2.f32 %0, %1, %2;" : "=r"(r) : "f"(hi), "f"(lo));
    return r;
}
__device__ __forceinline__ float ex2(float x) {
    float r;
    asm("ex2.approx.f32 %0, %1;" : "=f"(r) : "f"(x));
    return r;
}
__device__ __forceinline__ void mma_f16(
    float& d0, float& d1, float& d2, float& d3,
    uint32_t a0, uint32_t a1, uint32_t a2, uint32_t a3,
    uint32_t b0, uint32_t b1)
{
    asm volatile(
        "mma.sync.aligned.m16n8k16.row.col.f32.f16.f16.f32 "
        "{%0,%1,%2,%3}, {%4,%5,%6,%7}, {%8,%9}, {%0,%1,%2,%3};"
        : "+f"(d0), "+f"(d1), "+f"(d2), "+f"(d3)
        : "r"(a0), "r"(a1), "r"(a2), "r"(a3), "r"(b0), "r"(b1));
}
__device__ __forceinline__ void cp16(uint32_t saddr, const void* gptr) {
    asm volatile("cp.async.cg.shared.global [%0], [%1], 16;"
                 :: "r"(saddr), "l"(gptr));
}
__device__ __forceinline__ void ldsm4(uint32_t& r0, uint32_t& r1,
                                      uint32_t& r2, uint32_t& r3, uint32_t saddr)
{
    asm volatile("ldmatrix.sync.aligned.m8n8.x4.shared.b16 {%0,%1,%2,%3}, [%4];"
        : "=r"(r0), "=r"(r1), "=r"(r2), "=r"(r3) : "r"(saddr));
}

// ---------------------------------------------------------------------------
// fp32 -> fp16x2 bulk convert (single tensor, and paired via grid.z)
// ---------------------------------------------------------------------------
__global__ void cvt_h_kernel(const float4* __restrict__ src,
                             uint2* __restrict__ dst, int n4)
{
    int i = blockIdx.x * blockDim.x + threadIdx.x;
    if (i >= n4) return;
    float4 v = src[i];
    dst[i] = make_uint2(pack2(v.x, v.y), pack2(v.z, v.w));
}

__global__ void cvt_h2_kernel(const float4* __restrict__ s0, uint2* __restrict__ d0,
                              const float4* __restrict__ s1, uint2* __restrict__ d1,
                              int n4)
{
    int i = blockIdx.x * blockDim.x + threadIdx.x;
    if (i >= n4) return;
    const float4* s = blockIdx.z ? s1 : s0;
    uint2* d        = blockIdx.z ? d1 : d0;
    float4 v = s[i];
    d[i] = make_uint2(pack2(v.x, v.y), pack2(v.z, v.w));
}

// ===========================================================================
// FP16 GEMM (NT), ldmatrix fragment loads, 3-stage cp.async (R15 — keep).
// ===========================================================================
constexpr int SAPADH = 36;
constexpr int TILE_H = 128 * SAPADH;
constexpr int NSTG = 3;
constexpr int SMEM_GEMM = NSTG * 2 * TILE_H * 4;

template<int VMODE>
__device__ __forceinline__ void gemm_body_f16(
    const uint32_t* __restrict__ A, const uint32_t* __restrict__ B,
    float* __restrict__ C, __half* __restrict__ Vt,
    int M, int N, int K, int bx, int by, uint32_t* smem)
{
    const int K2 = K / 2;
    const int tid  = threadIdx.x;
    const int lane = tid & 31;
    const int wid  = tid >> 5;
    const int m0 = by * 128;
    const int n0 = bx * 128;

    const int wm  = (wid >> 2) * 64;
    const int wn  = (wid & 3) * 32;
    const int gID = lane >> 2;
    const int tig = lane & 3;

    const int lr0 = tid >> 3;
    const int lc4 = tid & 7;

    const int laneA_row = wm + (lane & 15);
    const int laneA_chk = (lane >> 4) * 4;
    const int laneB_row = wn + ((lane >> 4) & 1) * 8 + (lane & 7);
    const int laneB_chk = ((lane >> 3) & 1) * 4;

    const uint32_t* Abase = A + (size_t)(m0 + lr0) * K2 + lc4 * 4;
    const uint32_t* Bbase = B + (size_t)(n0 + lr0) * K2 + lc4 * 4;
    const uint32_t sbase = (uint32_t)__cvta_generic_to_shared(smem);

    float acc[4][4][4];
#pragma unroll
    for (int mi = 0; mi < 4; ++mi)
#pragma unroll
        for (int ni = 0; ni < 4; ++ni)
#pragma unroll
            for (int q = 0; q < 4; ++q) acc[mi][ni][q] = 0.f;

    const int nch = K / 64;

    auto issue = [&](int c) {
        const uint32_t st = sbase + (uint32_t)((c % NSTG) * 2 * TILE_H) * 4;
        const int kb = c * 32;
#pragma unroll
        for (int j = 0; j < 4; ++j) {
            int r = lr0 + 32 * j;
            cp16(st + (uint32_t)(r * SAPADH + lc4 * 4) * 4,
                 Abase + (size_t)(32 * j) * K2 + kb);
            cp16(st + (uint32_t)(TILE_H + r * SAPADH + lc4 * 4) * 4,
                 Bbase + (size_t)(32 * j) * K2 + kb);
        }
        asm volatile("cp.async.commit_group;");
    };

    issue(0);
    issue(1);

    for (int c = 0; c < nch; ++c) {
        if (c + 1 < nch) asm volatile("cp.async.wait_group 1;");
        else             asm volatile("cp.async.wait_group 0;");
        __syncthreads();

        const uint32_t stg = sbase + (uint32_t)((c % NSTG) * 2 * TILE_H) * 4;
        const uint32_t aA = stg + (uint32_t)(laneA_row * SAPADH + laneA_chk) * 4;
        const uint32_t aB = stg + (uint32_t)(TILE_H + laneB_row * SAPADH + laneB_chk) * 4;

#pragma unroll
        for (int ks = 0; ks < 4; ++ks) {
            uint32_t af[4][4], bf[4][2];
            ldsm4(af[0][0], af[0][1], af[0][2], af[0][3], aA + ks * 32);
            ldsm4(af[1][0], af[1][1], af[1][2], af[1][3], aA + 16 * SAPADH * 4 + ks * 32);
            ldsm4(af[2][0], af[2][1], af[2][2], af[2][3], aA + 32 * SAPADH * 4 + ks * 32);
            ldsm4(af[3][0], af[3][1], af[3][2], af[3][3], aA + 48 * SAPADH * 4 + ks * 32);
            ldsm4(bf[0][0], bf[0][1], bf[1][0], bf[1][1], aB + ks * 32);
            ldsm4(bf[2][0], bf[2][1], bf[3][0], bf[3][1], aB + 16 * SAPADH * 4 + ks * 32);
#pragma unroll
            for (int mi = 0; mi < 4; ++mi)
#pragma unroll
                for (int ni = 0; ni < 4; ++ni)
                    mma_f16(acc[mi][ni][0], acc[mi][ni][1], acc[mi][ni][2], acc[mi][ni][3],
                            af[mi][0], af[mi][1], af[mi][2], af[mi][3],
                            bf[ni][0], bf[ni][1]);
        }

        if (c + 2 < nch) issue(c + 2);
    }

    if (VMODE == 0) {
#pragma unroll
        for (int mi = 0; mi < 4; ++mi) {
            int row = m0 + wm + mi * 16 + gID;
#pragma unroll
            for (int ni = 0; ni < 4; ++ni) {
                int col = n0 + wn + ni * 8 + tig * 2;
                *reinterpret_cast<float2*>(C + (size_t)row * N + col) =
                    make_float2(acc[mi][ni][0], acc[mi][ni][1]);
                *reinterpret_cast<float2*>(C + (size_t)(row + 8) * N + col) =
                    make_float2(acc[mi][ni][2], acc[mi][ni][3]);
            }
        }
    } else {
#pragma unroll
        for (int mi = 0; mi < 4; ++mi) {
            int row = m0 + wm + mi * 16 + gID;
            int b0i = row >> 11, s0i = row & 2047;
            int b1i = (row + 8) >> 11, s1i = (row + 8) & 2047;
#pragma unroll
            for (int ni = 0; ni < 4; ++ni) {
                int col = n0 + wn + ni * 8 + tig * 2;
#pragma unroll
                for (int cc = 0; cc < 2; ++cc) {
                    int n = col + cc;
                    int kv = n >> 7, d = n & 127;
                    size_t base = ((size_t)(b0i * NKVH + kv) * HDIM + d) * SEQ;
                    Vt[base + s0i] = __float2half_rn(acc[mi][ni][cc]);
                    size_t base1 = ((size_t)(b1i * NKVH + kv) * HDIM + d) * SEQ;
                    Vt[base1 + s1i] = __float2half_rn(acc[mi][ni][cc + 2]);
                }
            }
        }
    }
}

__global__ __launch_bounds__(256, 2) void gemm_f16(
    const uint32_t* __restrict__ A, const uint32_t* __restrict__ B,
    float* __restrict__ C, int M, int N, int K)
{
    extern __shared__ uint32_t smem[];
    gemm_body_f16<0>(A, B, C, nullptr, M, N, K, blockIdx.x, blockIdx.y, smem);
}

__global__ __launch_bounds__(256, 2) void gemm_kv_f16(
    const uint32_t* __restrict__ A,
    const uint32_t* __restrict__ Wk, const uint32_t* __restrict__ Wv,
    float* __restrict__ Kout, __half* __restrict__ Vt,
    int M, int N, int K)
{
    extern __shared__ uint32_t smem[];
    if (blockIdx.z == 0)
        gemm_body_f16<0>(A, Wk, Kout, nullptr, M, N, K, blockIdx.x, blockIdx.y, smem);
    else
        gemm_body_f16<1>(A, Wv, nullptr, Vt, M, N, K, blockIdx.x, blockIdx.y, smem);
}

// ---------------------------------------------------------------------------
// RoPE: fp32 in, pre-scaled fp16 out.
// ---------------------------------------------------------------------------
__global__ void rope_kernel(const float* __restrict__ cosb,
                            const float* __restrict__ sinb)
{
    const int total = BATCH * SEQ * (NHEADS + NKVH) * 32;
    int idx = blockIdx.x * blockDim.x + threadIdx.x;
    if (idx >= total) return;
    int e    = idx & 31;
    int rest = idx >> 5;
    int slot = rest % (NHEADS + NKVH);
    int bs   = rest / (NHEADS + NKVH);
    int s    = bs % SEQ;

    const float2* cp = reinterpret_cast<const float2*>(cosb + s * HDIM);
    const float2* sp = reinterpret_cast<const float2*>(sinb + s * HDIM);
    float2 c0 = cp[e], c1 = cp[e + 32];
    float2 s0 = sp[e], s1 = sp[e + 32];

    const float2* p;
    uint32_t* o;
    float mult;
    if (slot < NHEADS) {
        p = reinterpret_cast<const float2*>(g_Q + (size_t)(bs * NHEADS + slot) * HDIM);
        o = g_Qh + (size_t)(bs * NHEADS + slot) * 64;
        mult = 0.08838834764831845f * 1.4426950408889634f;
    } else {
        p = reinterpret_cast<const float2*>(g_K + (size_t)(bs * NKVH + (slot - NHEADS)) * HDIM);
        o = g_Kh + (size_t)(bs * NKVH + (slot - NHEADS)) * 64;
        mult = 1.0f;
    }

    float2 x0 = p[e];
    float2 x1 = p[e + 32];
    float o0x = x0.x * c0.x - x1.x * s0.x;
    float o0y = x0.y * c0.y - x1.y * s0.y;
    float o1x = x1.x * c1.x + x0.x * s1.x;
    float o1y = x1.y * c1.y + x0.y * s1.y;
    o[e]      = pack2(o0x * mult, o0y * mult);
    o[e + 32] = pack2(o1x * mult, o1y * mult);
}

// ===========================================================================
// FP16 MMA flash attention: 2 heads x 32 queries per CTA (128 threads, 4 warps).
// R16: ldmatrix fragment loads for K / V / P. Loop structure unchanged.
// ===========================================================================
constexpr int KSTRH = 68;
constexpr int VSTRH = 20;
constexpr int QSTRH = 68;
constexpr int PSTRH = 20;

constexpr int AKS0 = 0;
constexpr int AKS1 = AKS0 + 32 * KSTRH;
constexpr int AVS0 = AKS1 + 32 * KSTRH;
constexpr int AVS1 = AVS0 + 128 * VSTRH;
constexpr int AQS  = AVS1 + 128 * VSTRH;
constexpr int APS  = AQS + 64 * QSTRH;
constexpr int SMEM_ATTN = (APS + 4 * 16 * PSTRH) * 4;   // 60416 B

__global__ __launch_bounds__(128, 3) void attn_f16_kernel()
{
    extern __shared__ uint32_t sm[];

    const int tid  = threadIdx.x;
    const int lane = tid & 31;
    const int wid  = tid >> 5;
    const int hl   = wid >> 1;
    const int sub  = wid & 1;
    const int g    = lane >> 2;
    const int t    = lane & 3;

    const int q0  = blockIdx.x * 32;
    const int hp  = blockIdx.y;
    const int kvh = hp >> 1;
    const int b   = blockIdx.z;
    const int h   = hp * 2 + hl;
    const int bS  = b * SEQ;
    const int qw  = q0 + sub * 16;

    const uint32_t sbase = (uint32_t)__cvta_generic_to_shared(sm);

    // ldmatrix lane addressing (B-type for K/V; A-type for P)
    const int laneB_row = ((lane >> 4) & 1) * 8 + (lane & 7);
    const int laneB_chk = ((lane >> 3) & 1) * 4;
    const uint32_t aP = sbase + (uint32_t)(APS + wid * 16 * PSTRH +
                        (lane & 15) * PSTRH + (lane >> 4) * 4) * 4;

    // ---- stage Q tiles for the 2 heads ----
#pragma unroll
    for (int i = tid; i < 1024; i += 128) {
        int ih = i >> 9;
        int r  = (i >> 4) & 31;
        int ch = i & 15;
        const uint32_t* src = g_Qh +
            ((size_t)(bS + q0 + r) * NHEADS + hp * 2 + ih) * 64 + ch * 4;
        cp16(sbase + (uint32_t)(AQS + (ih * 32 + r) * QSTRH + ch * 4) * 4, src);
    }
    asm volatile("cp.async.commit_group;");

    // ---- stage first K/V tile ----
    int jstart = q0 - (WIN - 1);
    if (jstart < 0) jstart = 0;
    jstart &= ~31;
    const int nt = (q0 + 32 - jstart) >> 5;

    auto stage_kv = [&](int j0, int buf) {
        const int ko = buf ? AKS1 : AKS0;
        const int vo = buf ? AVS1 : AVS0;
#pragma unroll
        for (int i = tid; i < 512; i += 128) {
            int r = i >> 4, ch = i & 15;
            const uint32_t* src = g_Kh + ((size_t)(bS + j0 + r) * NKVH + kvh) * 64 + ch * 4;
            cp16(sbase + (uint32_t)(ko + r * KSTRH + ch * 4) * 4, src);
        }
        const uint32_t* Vt = reinterpret_cast<const uint32_t*>(g_Vth) +
            ((size_t)(b * NKVH + kvh) * HDIM) * (SEQ / 2);
#pragma unroll
        for (int i = tid; i < 512; i += 128) {
            int d = i >> 2, ch = i & 3;
            const uint32_t* src = Vt + (size_t)d * (SEQ / 2) + (j0 >> 1) + ch * 4;
            cp16(sbase + (uint32_t)(vo + d * VSTRH + ch * 4) * 4, src);
        }
        asm volatile("cp.async.commit_group;");
    };

    stage_kv(jstart, 0);

    asm volatile("cp.async.wait_group 1;");
    __syncthreads();
    uint32_t qf[8][4];
#pragma unroll
    for (int kk = 0; kk < 8; ++kk) {
        int r0 = AQS + (hl * 32 + sub * 16 + g) * QSTRH + kk * 8 + t;
        qf[kk][0] = sm[r0];
        qf[kk][1] = sm[r0 + 8 * QSTRH];
        qf[kk][2] = sm[r0 + 4];
        qf[kk][3] = sm[r0 + 8 * QSTRH + 4];
    }

    uint32_t* Pw = &sm[APS + wid * 16 * PSTRH];

    float m0r = -1e30f, m1r = -1e30f, l0 = 0.f, l1 = 0.f;
    float oacc[16][4];
#pragma unroll
    for (int ni = 0; ni < 16; ++ni)
#pragma unroll
        for (int qd = 0; qd < 4; ++qd) oacc[ni][qd] = 0.f;

    for (int it = 0; it < nt; ++it) {
        const int j0 = jstart + it * 32;
        if (it + 1 < nt) {
            stage_kv(j0 + 32, (it + 1) & 1);
            asm volatile("cp.async.wait_group 1;");
        } else {
            asm volatile("cp.async.wait_group 0;");
        }
        __syncthreads();

        const bool active = (j0 <= qw + 15) && (qw - (j0 + 31) < WIN);
        if (active) {
            const int ko = (it & 1) ? AKS1 : AKS0;
            const int vo = (it & 1) ? AVS1 : AVS0;
            const uint32_t aK = sbase + (uint32_t)(ko + laneB_row * KSTRH + laneB_chk) * 4;
            const uint32_t aV = sbase + (uint32_t)(vo + laneB_row * VSTRH + laneB_chk) * 4;

            // ---- QK^T (ldmatrix K fragments) ----
            float sc[4][4];
#pragma unroll
            for (int ni = 0; ni < 4; ++ni)
#pragma unroll
                for (int qd = 0; qd < 4; ++qd) sc[ni][qd] = 0.f;

#pragma unroll
            for (int kk = 0; kk < 8; ++kk) {
                uint32_t bk[8];
                ldsm4(bk[0], bk[1], bk[2], bk[3], aK + kk * 32);
                ldsm4(bk[4], bk[5], bk[6], bk[7], aK + 16 * KSTRH * 4 + kk * 32);
                mma_f16(sc[0][0], sc[0][1], sc[0][2], sc[0][3],
                        qf[kk][0], qf[kk][1], qf[kk][2], qf[kk][3], bk[0], bk[1]);
                mma_f16(sc[1][0], sc[1][1], sc[1][2], sc[1][3],
                        qf[kk][0], qf[kk][1], qf[kk][2], qf[kk][3], bk[2], bk[3]);
                mma_f16(sc[2][0], sc[2][1], sc[2][2], sc[2][3],
                        qf[kk][0], qf[kk][1], qf[kk][2], qf[kk][3], bk[4], bk[5]);
                mma_f16(sc[3][0], sc[3][1], sc[3][2], sc[3][3],
                        qf[kk][0], qf[kk][1], qf[kk][2], qf[kk][3], bk[6], bk[7]);
            }

            // ---- mask + row max ----
            const int r0 = qw + g;
            float tmax0 = -1e30f, tmax1 = -1e30f;
#pragma unroll
            for (int ni = 0; ni < 4; ++ni) {
                int col0 = j0 + ni * 8 + 2 * t;
#pragma unroll
                for (int cc = 0; cc < 2; ++cc) {
                    int col = col0 + cc;
                    int d0 = r0 - col;
                    int d1 = r0 + 8 - col;
                    if (!(d0 >= 0 && d0 < WIN)) sc[ni][cc]     = -1e30f;
                    if (!(d1 >= 0 && d1 < WIN)) sc[ni][cc + 2] = -1e30f;
                    tmax0 = fmaxf(tmax0, sc[ni][cc]);
                    tmax1 = fmaxf(tmax1, sc[ni][cc + 2]);
                }
            }
            tmax0 = fmaxf(tmax0, __shfl_xor_sync(0xffffffffu, tmax0, 1));
            tmax0 = fmaxf(tmax0, __shfl_xor_sync(0xffffffffu, tmax0, 2));
            tmax1 = fmaxf(tmax1, __shfl_xor_sync(0xffffffffu, tmax1, 1));
            tmax1 = fmaxf(tmax1, __shfl_xor_sync(0xffffffffu, tmax1, 2));

            float mn0 = fmaxf(m0r, tmax0);
            float mn1 = fmaxf(m1r, tmax1);
            float cor0 = ex2(m0r - mn0);
            float cor1 = ex2(m1r - mn1);
            m0r = mn0; m1r = mn1;

            float ps0 = 0.f, ps1 = 0.f;
#pragma unroll
            for (int ni = 0; ni < 4; ++ni) {
                float p00 = (sc[ni][0] > -1e29f) ? ex2(sc[ni][0] - mn0) : 0.f;
                float p01 = (sc[ni][1] > -1e29f) ? ex2(sc[ni][1] - mn0) : 0.f;
                float p10 = (sc[ni][2] > -1e29f) ? ex2(sc[ni][2] - mn1) : 0.f;
                float p11 = (sc[ni][3] > -1e29f) ? ex2(sc[ni][3] - mn1) : 0.f;
                ps0 += p00 + p01;
                ps1 += p10 + p11;
                Pw[g * PSTRH + ni * 4 + t]       = pack2(p00, p01);
                Pw[(g + 8) * PSTRH + ni * 4 + t] = pack2(p10, p11);
            }
            ps0 += __shfl_xor_sync(0xffffffffu, ps0, 1);
            ps0 += __shfl_xor_sync(0xffffffffu, ps0, 2);
            ps1 += __shfl_xor_sync(0xffffffffu, ps1, 1);
            ps1 += __shfl_xor_sync(0xffffffffu, ps1, 2);
            l0 = l0 * cor0 + ps0;
            l1 = l1 * cor1 + ps1;

#pragma unroll
            for (int ni = 0; ni < 16; ++ni) {
                oacc[ni][0] *= cor0; oacc[ni][1] *= cor0;
                oacc[ni][2] *= cor1; oacc[ni][3] *= cor1;
            }

            __syncwarp();

            // ---- PV (ldmatrix P + V fragments) ----
#pragma unroll
            for (int kc = 0; kc < 2; ++kc) {
                uint32_t ap[4];
                ldsm4(ap[0], ap[1], ap[2], ap[3], aP + kc * 32);
#pragma unroll
                for (int p = 0; p < 8; ++p) {
                    uint32_t bv[4];
                    ldsm4(bv[0], bv[1], bv[2], bv[3],
                          aV + (uint32_t)(p * 16 * VSTRH) * 4 + kc * 32);
                    mma_f16(oacc[2 * p][0], oacc[2 * p][1], oacc[2 * p][2], oacc[2 * p][3],
                            ap[0], ap[1], ap[2], ap[3], bv[0], bv[1]);
                    mma_f16(oacc[2 * p + 1][0], oacc[2 * p + 1][1],
                            oacc[2 * p + 1][2], oacc[2 * p + 1][3],
                            ap[0], ap[1], ap[2], ap[3], bv[2], bv[3]);
                }
            }
            __syncwarp();
        }
        __syncthreads();
    }

    // ---- normalize + store half2 for O-projection ----
    float inv0 = 1.f / l0;
    float inv1 = 1.f / l1;
    uint32_t* Ot  = g_AOh + ((size_t)(bS + qw + g) * NHEADS + h) * 64;
    uint32_t* Ot8 = Ot + (size_t)8 * NHEADS * 64;
#pragma unroll
    for (int ni = 0; ni < 16; ++ni) {
        Ot[ni * 4 + t]  = pack2(oacc[ni][0] * inv0, oacc[ni][1] * inv0);
        Ot8[ni * 4 + t] = pack2(oacc[ni][2] * inv1, oacc[ni][3] * inv1);
    }
}

// ---------------------------------------------------------------------------
// Launch
// ---------------------------------------------------------------------------
extern "C" void kernel_launch(void* const* d_in, const int* in_sizes, int n_in,
                              void* d_out, int out_size)
{
    const float* x    = (const float*)d_in[0];
    const float* cosb = (const float*)d_in[1];
    const float* sinb = (const float*)d_in[2];
    const float* Wq   = (const float*)d_in[3];
    const float* Wk   = (const float*)d_in[4];
    const float* Wv   = (const float*)d_in[5];
    const float* Wo   = (const float*)d_in[6];
    float* out = (float*)d_out;

    float *Q, *K;
    uint32_t *xh, *Wqh, *Wkh, *Wvh, *Woh, *AOh;
    __half* Vth;
    cudaGetSymbolAddress((void**)&Q,   g_Q);
    cudaGetSymbolAddress((void**)&K,   g_K);
    cudaGetSymbolAddress((void**)&xh,  g_xh);
    cudaGetSymbolAddress((void**)&Wqh, g_Wqh);
    cudaGetSymbolAddress((void**)&Wkh, g_Wkh);
    cudaGetSymbolAddress((void**)&Wvh, g_Wvh);
    cudaGetSymbolAddress((void**)&Woh, g_Woh);
    cudaGetSymbolAddress((void**)&AOh, g_AOh);
    cudaGetSymbolAddress((void**)&Vth, g_Vth);

    static bool attr_done = false;
    if (!attr_done) {
        cudaFuncSetAttribute(gemm_f16,    cudaFuncAttributeMaxDynamicSharedMemorySize, SMEM_GEMM);
        cudaFuncSetAttribute(gemm_kv_f16, cudaFuncAttributeMaxDynamicSharedMemorySize, SMEM_GEMM);
        cudaFuncSetAttribute(attn_f16_kernel, cudaFuncAttributeMaxDynamicSharedMemorySize, SMEM_ATTN);
        attr_done = true;
    }

    const int M = BATCH * SEQ;

    // x convert (single), then paired weight converts (grid.z selects)
    {
        int n4x = BATCH * SEQ * EMB / 4;
        cvt_h_kernel<<<(n4x + 255) / 256, 256>>>(
            reinterpret_cast<const float4*>(x), reinterpret_cast<uint2*>(xh), n4x);

        int n4w = EMB * EMB / 4;
        cvt_h2_kernel<<<dim3((n4w + 255) / 256, 1, 2), 256>>>(
            reinterpret_cast<const float4*>(Wq), reinterpret_cast<uint2*>(Wqh),
            reinterpret_cast<const float4*>(Wo), reinterpret_cast<uint2*>(Woh), n4w);

        int n4kv = NKVH * HDIM * EMB / 4;
        cvt_h2_kernel<<<dim3((n4kv + 255) / 256, 1, 2), 256>>>(
            reinterpret_cast<const float4*>(Wk), reinterpret_cast<uint2*>(Wkh),
            reinterpret_cast<const float4*>(Wv), reinterpret_cast<uint2*>(Wvh), n4kv);
    }

    // Q projection (fp32 out, rope converts)
    gemm_f16<<<dim3(EMB / 128, M / 128), 256, SMEM_GEMM>>>(xh, Wqh, Q, M, NHEADS * HDIM, EMB);
    // K (fp32 out) + V (fp16 transposed out) fused
    gemm_kv_f16<<<dim3((NKVH * HDIM) / 128, M / 128, 2), 256, SMEM_GEMM>>>(
        xh, Wkh, Wvh, K, Vth, M, NKVH * HDIM, EMB);

    {
        int total = BATCH * SEQ * (NHEADS + NKVH) * 32;
        rope_kernel<<<(total + 255) / 256, 256>>>(cosb, sinb);
    }

    // 2 heads per CTA, 128 threads (best attention config) + ldmatrix
    attn_f16_kernel<<<dim3(SEQ / 32, NHEADS / 2, BATCH), 128, SMEM_ATTN>>>();

    // Output projection (A = attention output fp16)
    gemm_f16<<<dim3(EMB / 128, M / 128), 256, SMEM_GEMM>>>(AOh, Woh, out, M, EMB, EMB);
}